// round 2
// baseline (speedup 1.0000x reference)
#include <cuda_runtime.h>
#include <math.h>

#define MROWS 1024
#define DIM   4096
#define NOUT  5
#define NELEM_W (DIM * DIM)   // 16777216

#define NHLOG2PI (-0.918938533204672741780329736406)
#define DPI 3.14159265358979323846

// ---------------- scratch (device globals; no allocations allowed) ----------------
__device__ float  g_h1[MROWS * DIM];
__device__ float  g_h2[MROWS * DIM];
__device__ double g_part[2][1024];   // per-block partial sums of squares for w1, w2
__device__ double g_small[4];        // [0]=sum b1^2, [1]=sum b2^2, [2]=lvp3 sum, [3]=lp3 sum
__device__ float  g_scales[4];       // [0]=1/||w1||, [1]=1/||b1||, [2]=1/||w2||, [3]=1/||b2||

// ---------------- block reduce helper (deterministic) ----------------
__device__ __forceinline__ double block_reduce_256(double v) {
    __shared__ double sm[256];
    int t = threadIdx.x;
    sm[t] = v;
    __syncthreads();
    for (int s = 128; s > 0; s >>= 1) {
        if (t < s) sm[t] += sm[t + s];
        __syncthreads();
    }
    double r = sm[0];
    __syncthreads();
    return r;
}

// ---------------- big sum-of-squares: stage 1 (per-block partials) ----------------
__global__ void sumsq_partial_kernel(const float* __restrict__ v, int n, int slot) {
    double acc = 0.0;
    int stride = gridDim.x * blockDim.x;
    for (int i = blockIdx.x * blockDim.x + threadIdx.x; i < n; i += stride) {
        double x = (double)v[i];
        acc += x * x;
    }
    double r = block_reduce_256(acc);
    if (threadIdx.x == 0) g_part[slot][blockIdx.x] = r;
}

// ---------------- small reductions (one block) ----------------
__global__ void small_sums_kernel(const float* __restrict__ b1,
                                  const float* __restrict__ b2,
                                  const float* __restrict__ w3mu,
                                  const float* __restrict__ w3rho,
                                  const float* __restrict__ b3mu,
                                  const float* __restrict__ b3rho) {
    int t = threadIdx.x;
    double a;

    // sum b1^2
    a = 0.0;
    for (int i = t; i < DIM; i += 256) { double x = (double)b1[i]; a += x * x; }
    {
        double r = block_reduce_256(a);
        if (t == 0) g_small[0] = r;
    }
    // sum b2^2
    a = 0.0;
    for (int i = t; i < DIM; i += 256) { double x = (double)b2[i]; a += x * x; }
    {
        double r = block_reduce_256(a);
        if (t == 0) g_small[1] = r;
    }
    // lvp3 = sum over rho of (NHLOG2PI - log(log1p(exp(rho))))
    a = 0.0;
    for (int i = t; i < NOUT * DIM; i += 256) {
        double r3 = (double)w3rho[i];
        a += NHLOG2PI - log(log1p(exp(r3)));
    }
    for (int i = t; i < NOUT; i += 256) {
        double r3 = (double)b3rho[i];
        a += NHLOG2PI - log(log1p(exp(r3)));
    }
    {
        double r = block_reduce_256(a);
        if (t == 0) g_small[2] = r;
    }
    // lp3 = sum over mu of (NHLOG2PI - 0.5*mu^2)
    a = 0.0;
    for (int i = t; i < NOUT * DIM; i += 256) {
        double m = (double)w3mu[i];
        a += NHLOG2PI - 0.5 * m * m;
    }
    for (int i = t; i < NOUT; i += 256) {
        double m = (double)b3mu[i];
        a += NHLOG2PI - 0.5 * m * m;
    }
    {
        double r = block_reduce_256(a);
        if (t == 0) g_small[3] = r;
    }
}

// ---------------- scalar math ----------------
__device__ double log_C_vmf(double d, double kappa) {
    double s  = 0.5 * d - 1.0;
    double x  = kappa / s;
    double sq = sqrt(1.0 + x * x);
    double eta = sq + log(x) - log1p(sq);
    double lbi = s * eta - 0.5 * log(2.0 * DPI * s) - 0.5 * log(sq);
    return d * NHLOG2PI + s * log(kappa) - lbi;
}

__device__ double log_surf(double d) {
    double h = 0.5 * (d + 1.0);
    return log(2.0) + h * log(DPI) - lgamma(h);
}

// ---------------- finalize: reduce partials, compute scales + lvp/lp ----------------
__global__ void finalize_kernel(const float* __restrict__ lkw1,
                                const float* __restrict__ lkb1,
                                const float* __restrict__ lkw2,
                                const float* __restrict__ lkb2,
                                float* __restrict__ out_scalars) {
    int t = threadIdx.x;
    double a;

    a = 0.0;
    for (int i = t; i < 1024; i += 256) a += g_part[0][i];
    double sw1 = block_reduce_256(a);

    a = 0.0;
    for (int i = t; i < 1024; i += 256) a += g_part[1][i];
    double sw2 = block_reduce_256(a);

    if (t == 0) {
        g_scales[0] = (float)(1.0 / sqrt(sw1));
        g_scales[1] = (float)(1.0 / sqrt(g_small[0]));
        g_scales[2] = (float)(1.0 / sqrt(sw2));
        g_scales[3] = (float)(1.0 / sqrt(g_small[1]));

        double kw1 = exp((double)lkw1[0]) + 1e-6;
        double kb1 = exp((double)lkb1[0]) + 1e-6;
        double kw2 = exp((double)lkw2[0]) + 1e-6;
        double kb2 = exp((double)lkb2[0]) + 1e-6;
        double dw = (double)NELEM_W;   // 4096*4096
        double db = (double)DIM;

        // vMF: kappa * <mu,mu> with <mu,mu> == 1
        double lvp = kw1 + log_C_vmf(dw, kw1) + kb1 + log_C_vmf(db, kb1)
                   + kw2 + log_C_vmf(dw, kw2) + kb2 + log_C_vmf(db, kb2)
                   + g_small[2];
        // source bug preserved: both vMF prior terms use d_w, for both layers
        double lp = -4.0 * log_surf(dw) + g_small[3];

        out_scalars[0] = (float)lvp;
        out_scalars[1] = (float)lp;
    }
}

// ---------------- fused SGEMM + scale + bias + relu ----------------
// C[M,N] = relu( (A[M,K] @ W[K,N]) * inv_norm_w + bvec[n] * inv_norm_b )
// Tiles: BM=128, BN=128, BK=8; 256 threads; 8x8 per-thread micro-tile.
__global__ void __launch_bounds__(256, 2)
gemm_relu_kernel(int a_sel, const float* __restrict__ Aext,
                 const float* __restrict__ W,
                 const float* __restrict__ bvec,
                 int sidx, int c_sel) {
    const int K = DIM, N = DIM;
    const float* A = a_sel ? g_h1 : Aext;
    float* C = c_sel ? g_h2 : g_h1;

    __shared__ float As[8][128];
    __shared__ float Ws[8][128];

    const int tid = threadIdx.x;
    const int tc = tid & 15;    // 0..15 over N
    const int tr = tid >> 4;    // 0..15 over M

    const int a_row = tid >> 1;         // 0..127
    const int a_col = (tid & 1) << 2;   // 0 or 4
    const int w_row = tid >> 5;         // 0..7
    const int w_col = (tid & 31) << 2;  // 0..124

    const float* Ablk = A + (size_t)blockIdx.y * 128 * K;
    const float* Wblk = W + (size_t)blockIdx.x * 128;

    float acc[8][8];
#pragma unroll
    for (int i = 0; i < 8; i++)
#pragma unroll
        for (int j = 0; j < 8; j++) acc[i][j] = 0.0f;

    for (int k0 = 0; k0 < K; k0 += 8) {
        float4 av = *(const float4*)(Ablk + (size_t)a_row * K + k0 + a_col);
        As[a_col + 0][a_row] = av.x;
        As[a_col + 1][a_row] = av.y;
        As[a_col + 2][a_row] = av.z;
        As[a_col + 3][a_row] = av.w;
        *(float4*)(&Ws[w_row][w_col]) =
            *(const float4*)(Wblk + (size_t)(k0 + w_row) * N + w_col);
        __syncthreads();

#pragma unroll
        for (int kk = 0; kk < 8; kk++) {
            float4 a0 = *(const float4*)(&As[kk][tr * 8]);
            float4 a1 = *(const float4*)(&As[kk][tr * 8 + 4]);
            float4 b0 = *(const float4*)(&Ws[kk][tc * 8]);
            float4 b1 = *(const float4*)(&Ws[kk][tc * 8 + 4]);
            float ar[8] = {a0.x, a0.y, a0.z, a0.w, a1.x, a1.y, a1.z, a1.w};
            float br[8] = {b0.x, b0.y, b0.z, b0.w, b1.x, b1.y, b1.z, b1.w};
#pragma unroll
            for (int i = 0; i < 8; i++)
#pragma unroll
                for (int j = 0; j < 8; j++)
                    acc[i][j] = fmaf(ar[i], br[j], acc[i][j]);
        }
        __syncthreads();
    }

    const float invw = g_scales[sidx];
    const float invb = g_scales[sidx + 1];
    const int row0 = blockIdx.y * 128 + tr * 8;
    const int col0 = blockIdx.x * 128 + tc * 8;

    float bv[8];
#pragma unroll
    for (int j = 0; j < 8; j++) bv[j] = bvec[col0 + j] * invb;

#pragma unroll
    for (int i = 0; i < 8; i++) {
        float* crow = C + (size_t)(row0 + i) * N + col0;
#pragma unroll
        for (int j = 0; j < 8; j += 4) {
            float4 v;
            v.x = fmaxf(acc[i][j + 0] * invw + bv[j + 0], 0.0f);
            v.y = fmaxf(acc[i][j + 1] * invw + bv[j + 1], 0.0f);
            v.z = fmaxf(acc[i][j + 2] * invw + bv[j + 2], 0.0f);
            v.w = fmaxf(acc[i][j + 3] * invw + bv[j + 3], 0.0f);
            *(float4*)(crow + j) = v;
        }
    }
}

// ---------------- layer 3 (tiny GEMM) + log_softmax, one warp per row ----------------
__global__ void layer3_kernel(const float* __restrict__ w3,   // [5, 4096]
                              const float* __restrict__ b3,   // [5]
                              float* __restrict__ out) {      // [1024, 5]
    const int warp = threadIdx.x >> 5;
    const int lane = threadIdx.x & 31;
    const int row = blockIdx.x * (blockDim.x >> 5) + warp;
    if (row >= MROWS) return;

    float acc[NOUT] = {0.f, 0.f, 0.f, 0.f, 0.f};
    const float* hrow = g_h2 + (size_t)row * DIM;
    for (int k = lane; k < DIM; k += 32) {
        float h = hrow[k];
#pragma unroll
        for (int o = 0; o < NOUT; o++) acc[o] += h * w3[o * DIM + k];
    }
#pragma unroll
    for (int o = 0; o < NOUT; o++)
#pragma unroll
        for (int off = 16; off > 0; off >>= 1)
            acc[o] += __shfl_xor_sync(0xffffffffu, acc[o], off);

    if (lane == 0) {
        float y[NOUT];
        float m = -1e30f;
#pragma unroll
        for (int o = 0; o < NOUT; o++) {
            y[o] = acc[o] + b3[o];
            m = fmaxf(m, y[o]);
        }
        float s = 0.0f;
#pragma unroll
        for (int o = 0; o < NOUT; o++) s += expf(y[o] - m);
        float lse = m + logf(s);
#pragma unroll
        for (int o = 0; o < NOUT; o++) out[row * NOUT + o] = y[o] - lse;
    }
}

// ---------------- launch ----------------
extern "C" void kernel_launch(void* const* d_in, const int* in_sizes, int n_in,
                              void* d_out, int out_size) {
    const float* x     = (const float*)d_in[0];
    const float* w1    = (const float*)d_in[1];
    const float* lkw1  = (const float*)d_in[2];
    const float* b1    = (const float*)d_in[3];
    const float* lkb1  = (const float*)d_in[4];
    const float* w2    = (const float*)d_in[5];
    const float* lkw2  = (const float*)d_in[6];
    const float* b2    = (const float*)d_in[7];
    const float* lkb2  = (const float*)d_in[8];
    const float* w3mu  = (const float*)d_in[9];
    const float* w3rho = (const float*)d_in[10];
    const float* b3mu  = (const float*)d_in[11];
    const float* b3rho = (const float*)d_in[12];
    float* out = (float*)d_out;

    // scalar path (deterministic two-stage double reductions)
    sumsq_partial_kernel<<<1024, 256>>>(w1, NELEM_W, 0);
    sumsq_partial_kernel<<<1024, 256>>>(w2, NELEM_W, 1);
    small_sums_kernel<<<1, 256>>>(b1, b2, w3mu, w3rho, b3mu, b3rho);
    finalize_kernel<<<1, 256>>>(lkw1, lkb1, lkw2, lkb2, out + (out_size - 2));

    // main path
    dim3 grid(DIM / 128, MROWS / 128);
    gemm_relu_kernel<<<grid, 256>>>(0, x, w1, b1, 0, 0);        // x @ W1 -> g_h1
    gemm_relu_kernel<<<grid, 256>>>(1, nullptr, w2, b2, 2, 1);  // g_h1 @ W2 -> g_h2
    layer3_kernel<<<128, 256>>>(w3mu, b3mu, out);
}

// round 4
// speedup vs baseline: 2.1765x; 2.1765x over previous
#include <cuda_runtime.h>
#include <cuda_bf16.h>
#include <math.h>
#include <stdint.h>

#define MROWS 1024
#define DIM   4096
#define NOUT  5
#define NHLOG2PI (-0.918938533204672741780329736406)
#define DPI 3.14159265358979323846

// GEMM tiling (warp-MMA, mma.sync m16n8k16 bf16)
#define BM 128
#define BN 128
#define BK 32
#define NCHUNK (DIM / BK)        // 128
#define ROWB 80                  // padded row bytes (32 bf16 = 64B data + 16B pad)
#define A_HI 0
#define A_LO (128 * ROWB)        // 10240
#define B_HI (2 * 128 * ROWB)    // 20480
#define B_LO (3 * 128 * ROWB)    // 30720
#define STAGE_BYTES (4 * 128 * ROWB)   // 40960
#define SMEM_TOTAL (2 * STAGE_BYTES)   // 81920

// ---------------- scratch (device globals; no allocations allowed) ----------------
__device__ __nv_bfloat16 g_xhi[MROWS * DIM];
__device__ __nv_bfloat16 g_xlo[MROWS * DIM];
__device__ __nv_bfloat16 g_w1thi[DIM * DIM];
__device__ __nv_bfloat16 g_w1tlo[DIM * DIM];
__device__ __nv_bfloat16 g_w2thi[DIM * DIM];
__device__ __nv_bfloat16 g_w2tlo[DIM * DIM];
__device__ __nv_bfloat16 g_h1hi[MROWS * DIM];
__device__ __nv_bfloat16 g_h1lo[MROWS * DIM];
__device__ float  g_h2[MROWS * DIM];
__device__ double g_wpart[2][16384];
__device__ float  g_scales[4];   // 1/||w1||, 1/||b1||, 1/||w2||, 1/||b2||

// ---------------- PTX helpers ----------------
__device__ __forceinline__ uint32_t smem_u32(const void* p) {
    uint32_t a;
    asm("{ .reg .u64 t; cvta.to.shared.u64 t, %1; cvt.u32.u64 %0, t; }" : "=r"(a) : "l"(p));
    return a;
}
__device__ __forceinline__ void cpasync16(uint32_t dst, const void* src) {
    asm volatile("cp.async.cg.shared.global [%0], [%1], 16;" :: "r"(dst), "l"(src));
}
__device__ __forceinline__ void ldsm4(uint32_t& r0, uint32_t& r1, uint32_t& r2, uint32_t& r3,
                                      uint32_t addr) {
    asm volatile("ldmatrix.sync.aligned.m8n8.x4.shared.b16 {%0,%1,%2,%3}, [%4];"
                 : "=r"(r0), "=r"(r1), "=r"(r2), "=r"(r3) : "r"(addr));
}
__device__ __forceinline__ void mma_bf16(float* c, const uint32_t* a, const uint32_t* b) {
    asm volatile("mma.sync.aligned.m16n8k16.row.col.f32.bf16.bf16.f32 "
                 "{%0,%1,%2,%3}, {%4,%5,%6,%7}, {%8,%9}, {%0,%1,%2,%3};"
                 : "+f"(c[0]), "+f"(c[1]), "+f"(c[2]), "+f"(c[3])
                 : "r"(a[0]), "r"(a[1]), "r"(a[2]), "r"(a[3]), "r"(b[0]), "r"(b[1]));
}

// ---------------- block reduce (deterministic) ----------------
__device__ __forceinline__ double block_reduce_256(double v) {
    __shared__ double sm[256];
    int t = threadIdx.x + threadIdx.y * blockDim.x;
    sm[t] = v;
    __syncthreads();
    for (int s = 128; s > 0; s >>= 1) {
        if (t < s) sm[t] += sm[t + s];
        __syncthreads();
    }
    double r = sm[0];
    __syncthreads();
    return r;
}

// ---------------- weight convert: f32 [K][N] -> bf16 hi/lo transposed [N][K] + sumsq ----------------
__global__ void convert_w_kernel(const float* __restrict__ W,
                                 __nv_bfloat16* __restrict__ Thi,
                                 __nv_bfloat16* __restrict__ Tlo,
                                 int slot) {
    __shared__ float tile[32][33];
    const int tx = threadIdx.x, ty = threadIdx.y;
    const int k0 = blockIdx.y * 32, n0 = blockIdx.x * 32;
    double ss = 0.0;
#pragma unroll
    for (int r = ty; r < 32; r += 8) {
        float v = W[(size_t)(k0 + r) * DIM + n0 + tx];
        tile[r][tx] = v;
        ss += (double)v * (double)v;
    }
    __syncthreads();
#pragma unroll
    for (int r = ty; r < 32; r += 8) {
        float v = tile[tx][r];                         // = W[k0+tx][n0+r]
        __nv_bfloat16 hi = __float2bfloat16(v);
        __nv_bfloat16 lo = __float2bfloat16(v - __bfloat162float(hi));
        size_t o = (size_t)(n0 + r) * DIM + k0 + tx;
        Thi[o] = hi;
        Tlo[o] = lo;
    }
    double r = block_reduce_256(ss);
    int t = ty * 32 + tx;
    if (t == 0) g_wpart[slot][blockIdx.y * 128 + blockIdx.x] = r;
}

// ---------------- x convert: f32 -> bf16 hi/lo ----------------
__global__ void convert_x_kernel(const float4* __restrict__ x) {
    const int n4 = MROWS * DIM / 4;
    __nv_bfloat162* xh = (__nv_bfloat162*)g_xhi;
    __nv_bfloat162* xl = (__nv_bfloat162*)g_xlo;
    for (int i = blockIdx.x * blockDim.x + threadIdx.x; i < n4; i += gridDim.x * blockDim.x) {
        float4 v = x[i];
        __nv_bfloat16 h0 = __float2bfloat16(v.x), h1 = __float2bfloat16(v.y);
        __nv_bfloat16 h2 = __float2bfloat16(v.z), h3 = __float2bfloat16(v.w);
        __nv_bfloat16 l0 = __float2bfloat16(v.x - __bfloat162float(h0));
        __nv_bfloat16 l1 = __float2bfloat16(v.y - __bfloat162float(h1));
        __nv_bfloat16 l2 = __float2bfloat16(v.z - __bfloat162float(h2));
        __nv_bfloat16 l3 = __float2bfloat16(v.w - __bfloat162float(h3));
        xh[i * 2 + 0] = __halves2bfloat162(h0, h1);
        xh[i * 2 + 1] = __halves2bfloat162(h2, h3);
        xl[i * 2 + 0] = __halves2bfloat162(l0, l1);
        xl[i * 2 + 1] = __halves2bfloat162(l2, l3);
    }
}

// ---------------- scalar math ----------------
__device__ double log_C_vmf(double d, double kappa) {
    double s  = 0.5 * d - 1.0;
    double x  = kappa / s;
    double sq = sqrt(1.0 + x * x);
    double eta = sq + log(x) - log1p(sq);
    double lbi = s * eta - 0.5 * log(2.0 * DPI * s) - 0.5 * log(sq);
    return d * NHLOG2PI + s * log(kappa) - lbi;
}
__device__ double log_surf(double d) {
    double h = 0.5 * (d + 1.0);
    return log(2.0) + h * log(DPI) - lgamma(h);
}

// ---------------- finalize: reductions + scales + lvp/lp ----------------
__global__ void finalize_all_kernel(const float* __restrict__ b1, const float* __restrict__ b2,
                                    const float* __restrict__ w3mu, const float* __restrict__ w3rho,
                                    const float* __restrict__ b3mu, const float* __restrict__ b3rho,
                                    const float* __restrict__ lkw1, const float* __restrict__ lkb1,
                                    const float* __restrict__ lkw2, const float* __restrict__ lkb2,
                                    float* __restrict__ out_scalars) {
    int t = threadIdx.x;
    double a;

    a = 0.0; for (int i = t; i < 16384; i += 256) a += g_wpart[0][i];
    double sw1 = block_reduce_256(a);
    a = 0.0; for (int i = t; i < 16384; i += 256) a += g_wpart[1][i];
    double sw2 = block_reduce_256(a);
    a = 0.0; for (int i = t; i < DIM; i += 256) { double x = (double)b1[i]; a += x * x; }
    double sb1 = block_reduce_256(a);
    a = 0.0; for (int i = t; i < DIM; i += 256) { double x = (double)b2[i]; a += x * x; }
    double sb2 = block_reduce_256(a);

    a = 0.0;
    for (int i = t; i < NOUT * DIM; i += 256) {
        float r = w3rho[i];
        a += (double)(-0.918938533f - logf(log1pf(expf(r))));
    }
    for (int i = t; i < NOUT; i += 256) {
        float r = b3rho[i];
        a += (double)(-0.918938533f - logf(log1pf(expf(r))));
    }
    double lvp3 = block_reduce_256(a);
    a = 0.0;
    for (int i = t; i < NOUT * DIM; i += 256) {
        float m = w3mu[i];
        a += (double)(-0.918938533f - 0.5f * m * m);
    }
    for (int i = t; i < NOUT; i += 256) {
        float m = b3mu[i];
        a += (double)(-0.918938533f - 0.5f * m * m);
    }
    double lp3 = block_reduce_256(a);

    if (t == 0) {
        g_scales[0] = (float)(1.0 / sqrt(sw1));
        g_scales[1] = (float)(1.0 / sqrt(sb1));
        g_scales[2] = (float)(1.0 / sqrt(sw2));
        g_scales[3] = (float)(1.0 / sqrt(sb2));

        double kw1 = exp((double)lkw1[0]) + 1e-6;
        double kb1 = exp((double)lkb1[0]) + 1e-6;
        double kw2 = exp((double)lkw2[0]) + 1e-6;
        double kb2 = exp((double)lkb2[0]) + 1e-6;
        double dw = (double)DIM * (double)DIM;
        double db = (double)DIM;

        double lvp = kw1 + log_C_vmf(dw, kw1) + kb1 + log_C_vmf(db, kb1)
                   + kw2 + log_C_vmf(dw, kw2) + kb2 + log_C_vmf(db, kb2) + lvp3;
        double lp = -4.0 * log_surf(dw) + lp3;   // source bug preserved (all terms use d_w)

        out_scalars[0] = (float)lvp;
        out_scalars[1] = (float)lp;
    }
}

// ---------------- warp-MMA GEMM: C = relu((A @ B^T)*invw + bias*invb) ----------------
// A: [M][K] bf16 hi/lo (K-major). B: [N][K] bf16 hi/lo (K-major, pre-transposed weights).
// 3-split: Ahi*Bhi + Ahi*Blo + Alo*Bhi, fp32 accumulate in registers.
__device__ __forceinline__ void load_stage(uint32_t base,
                                           const __nv_bfloat16* __restrict__ Ahi,
                                           const __nv_bfloat16* __restrict__ Alo,
                                           const __nv_bfloat16* __restrict__ Bhi,
                                           const __nv_bfloat16* __restrict__ Blo,
                                           int m0, int n0, int k0, int tid) {
#pragma unroll
    for (int q = 0; q < 2; q++) {
        int c = tid + q * 256;
        int row = c >> 2, c16 = c & 3;
        uint32_t off = (uint32_t)(row * ROWB + c16 * 16);
        size_t asrc = (size_t)(m0 + row) * DIM + k0 + c16 * 8;
        size_t bsrc = (size_t)(n0 + row) * DIM + k0 + c16 * 8;
        cpasync16(base + A_HI + off, Ahi + asrc);
        cpasync16(base + A_LO + off, Alo + asrc);
        cpasync16(base + B_HI + off, Bhi + bsrc);
        cpasync16(base + B_LO + off, Blo + bsrc);
    }
}

__global__ void __launch_bounds__(256)
gemm_kernel(const __nv_bfloat16* __restrict__ Ahi, const __nv_bfloat16* __restrict__ Alo,
            const __nv_bfloat16* __restrict__ Bhi, const __nv_bfloat16* __restrict__ Blo,
            const float* __restrict__ bias, int sidx, int mode) {
    extern __shared__ char smem[];
    const uint32_t sb = smem_u32(smem);
    const int tid = threadIdx.x, wid = tid >> 5, lane = tid & 31;
    const int wm = wid >> 2, wn = wid & 3;     // 2 x 4 warp grid
    const int m0 = blockIdx.y * BM, n0 = blockIdx.x * BN;

    float acc[4][4][4];
#pragma unroll
    for (int i = 0; i < 4; i++)
#pragma unroll
        for (int j = 0; j < 4; j++)
#pragma unroll
            for (int k = 0; k < 4; k++) acc[i][j][k] = 0.0f;

    // ldmatrix per-thread addresses (within-stage offsets)
    const uint32_t a_row = (uint32_t)(wm * 64 + (lane & 15));          // + mt*16
    const uint32_t a_colh = (uint32_t)(lane >> 4);                     // k-half select
    const uint32_t b_row = (uint32_t)(wn * 32 + ((lane >> 4) & 1) * 8 + (lane & 7));  // + p*16
    const uint32_t b_colh = (uint32_t)((lane >> 3) & 1);

    load_stage(sb, Ahi, Alo, Bhi, Blo, m0, n0, 0, tid);
    asm volatile("cp.async.commit_group;" ::: "memory");

    for (int i = 0; i < NCHUNK; i++) {
        const uint32_t stg = sb + (uint32_t)(i & 1) * STAGE_BYTES;
        asm volatile("cp.async.wait_group 0;" ::: "memory");
        __syncthreads();
        if (i + 1 < NCHUNK) {
            load_stage(sb + (uint32_t)((i + 1) & 1) * STAGE_BYTES,
                       Ahi, Alo, Bhi, Blo, m0, n0, (i + 1) * BK, tid);
            asm volatile("cp.async.commit_group;" ::: "memory");
        }

#pragma unroll
        for (int ks = 0; ks < 2; ks++) {
            const uint32_t acol = (uint32_t)(ks * 2 + a_colh) * 16;
            const uint32_t bcol = (uint32_t)(ks * 2 + b_colh) * 16;

            uint32_t ah[4][4], bh[2][4];
#pragma unroll
            for (int mt = 0; mt < 4; mt++)
                ldsm4(ah[mt][0], ah[mt][1], ah[mt][2], ah[mt][3],
                      stg + A_HI + (a_row + mt * 16) * ROWB + acol);
#pragma unroll
            for (int p = 0; p < 2; p++)
                ldsm4(bh[p][0], bh[p][1], bh[p][2], bh[p][3],
                      stg + B_HI + (b_row + p * 16) * ROWB + bcol);

#pragma unroll
            for (int mt = 0; mt < 4; mt++)
#pragma unroll
                for (int nt = 0; nt < 4; nt++)
                    mma_bf16(acc[mt][nt], ah[mt], &bh[nt >> 1][(nt & 1) * 2]);

            {
                uint32_t bl[2][4];
#pragma unroll
                for (int p = 0; p < 2; p++)
                    ldsm4(bl[p][0], bl[p][1], bl[p][2], bl[p][3],
                          stg + B_LO + (b_row + p * 16) * ROWB + bcol);
#pragma unroll
                for (int mt = 0; mt < 4; mt++)
#pragma unroll
                    for (int nt = 0; nt < 4; nt++)
                        mma_bf16(acc[mt][nt], ah[mt], &bl[nt >> 1][(nt & 1) * 2]);
            }
            {
                uint32_t al[4][4];
#pragma unroll
                for (int mt = 0; mt < 4; mt++)
                    ldsm4(al[mt][0], al[mt][1], al[mt][2], al[mt][3],
                          stg + A_LO + (a_row + mt * 16) * ROWB + acol);
#pragma unroll
                for (int mt = 0; mt < 4; mt++)
#pragma unroll
                    for (int nt = 0; nt < 4; nt++)
                        mma_bf16(acc[mt][nt], al[mt], &bh[nt >> 1][(nt & 1) * 2]);
            }
        }
        __syncthreads();
    }

    // ------- epilogue: scale + bias + relu; direct fragment stores -------
    const float invw = g_scales[sidx];
    const float invb = g_scales[sidx + 1];
#pragma unroll
    for (int mt = 0; mt < 4; mt++) {
        const int r0 = m0 + wm * 64 + mt * 16 + (lane >> 2);
#pragma unroll
        for (int nt = 0; nt < 4; nt++) {
            const int col = n0 + wn * 32 + nt * 8 + 2 * (lane & 3);
            const float bv0 = bias[col] * invb;
            const float bv1 = bias[col + 1] * invb;
            float v00 = fmaxf(acc[mt][nt][0] * invw + bv0, 0.0f);
            float v01 = fmaxf(acc[mt][nt][1] * invw + bv1, 0.0f);
            float v10 = fmaxf(acc[mt][nt][2] * invw + bv0, 0.0f);
            float v11 = fmaxf(acc[mt][nt][3] * invw + bv1, 0.0f);
            const size_t o0 = (size_t)r0 * DIM + col;
            const size_t o1 = (size_t)(r0 + 8) * DIM + col;
            if (mode == 0) {
                __nv_bfloat16 h00 = __float2bfloat16(v00), h01 = __float2bfloat16(v01);
                __nv_bfloat16 h10 = __float2bfloat16(v10), h11 = __float2bfloat16(v11);
                *(__nv_bfloat162*)(g_h1hi + o0) = __halves2bfloat162(h00, h01);
                *(__nv_bfloat162*)(g_h1hi + o1) = __halves2bfloat162(h10, h11);
                *(__nv_bfloat162*)(g_h1lo + o0) = __halves2bfloat162(
                    __float2bfloat16(v00 - __bfloat162float(h00)),
                    __float2bfloat16(v01 - __bfloat162float(h01)));
                *(__nv_bfloat162*)(g_h1lo + o1) = __halves2bfloat162(
                    __float2bfloat16(v10 - __bfloat162float(h10)),
                    __float2bfloat16(v11 - __bfloat162float(h11)));
            } else {
                *(float2*)(g_h2 + o0) = make_float2(v00, v01);
                *(float2*)(g_h2 + o1) = make_float2(v10, v11);
            }
        }
    }
}

// ---------------- layer 3 (tiny GEMM) + log_softmax, one warp per row ----------------
__global__ void layer3_kernel(const float* __restrict__ w3,
                              const float* __restrict__ b3,
                              float* __restrict__ out) {
    const int warp = threadIdx.x >> 5;
    const int lane = threadIdx.x & 31;
    const int row = blockIdx.x * (blockDim.x >> 5) + warp;
    if (row >= MROWS) return;

    float acc[NOUT] = {0.f, 0.f, 0.f, 0.f, 0.f};
    const float* hrow = g_h2 + (size_t)row * DIM;
    for (int k = lane; k < DIM; k += 32) {
        float h = hrow[k];
#pragma unroll
        for (int o = 0; o < NOUT; o++) acc[o] += h * w3[o * DIM + k];
    }
#pragma unroll
    for (int o = 0; o < NOUT; o++)
#pragma unroll
        for (int off = 16; off > 0; off >>= 1)
            acc[o] += __shfl_xor_sync(0xffffffffu, acc[o], off);

    if (lane == 0) {
        float y[NOUT];
        float m = -1e30f;
#pragma unroll
        for (int o = 0; o < NOUT; o++) {
            y[o] = acc[o] + b3[o];
            m = fmaxf(m, y[o]);
        }
        float s = 0.0f;
#pragma unroll
        for (int o = 0; o < NOUT; o++) s += expf(y[o] - m);
        float lse = m + logf(s);
#pragma unroll
        for (int o = 0; o < NOUT; o++) out[row * NOUT + o] = y[o] - lse;
    }
}

// ---------------- launch ----------------
extern "C" void kernel_launch(void* const* d_in, const int* in_sizes, int n_in,
                              void* d_out, int out_size) {
    const float* x     = (const float*)d_in[0];
    const float* w1    = (const float*)d_in[1];
    const float* lkw1  = (const float*)d_in[2];
    const float* b1    = (const float*)d_in[3];
    const float* lkb1  = (const float*)d_in[4];
    const float* w2    = (const float*)d_in[5];
    const float* lkw2  = (const float*)d_in[6];
    const float* b2    = (const float*)d_in[7];
    const float* lkb2  = (const float*)d_in[8];
    const float* w3mu  = (const float*)d_in[9];
    const float* w3rho = (const float*)d_in[10];
    const float* b3mu  = (const float*)d_in[11];
    const float* b3rho = (const float*)d_in[12];
    float* out = (float*)d_out;

    static bool attr_done = false;
    if (!attr_done) {
        cudaFuncSetAttribute(gemm_kernel, cudaFuncAttributeMaxDynamicSharedMemorySize, SMEM_TOTAL);
        attr_done = true;
    }

    __nv_bfloat16 *p_xhi, *p_xlo, *p_w1thi, *p_w1tlo, *p_w2thi, *p_w2tlo, *p_h1hi, *p_h1lo;
    cudaGetSymbolAddress((void**)&p_xhi,  g_xhi);
    cudaGetSymbolAddress((void**)&p_xlo,  g_xlo);
    cudaGetSymbolAddress((void**)&p_w1thi, g_w1thi);
    cudaGetSymbolAddress((void**)&p_w1tlo, g_w1tlo);
    cudaGetSymbolAddress((void**)&p_w2thi, g_w2thi);
    cudaGetSymbolAddress((void**)&p_w2tlo, g_w2tlo);
    cudaGetSymbolAddress((void**)&p_h1hi, g_h1hi);
    cudaGetSymbolAddress((void**)&p_h1lo, g_h1lo);

    // conversions (w-conversion fuses sumsq partials)
    dim3 cgrid(128, 128), cblk(32, 8);
    convert_w_kernel<<<cgrid, cblk>>>(w1, p_w1thi, p_w1tlo, 0);
    convert_w_kernel<<<cgrid, cblk>>>(w2, p_w2thi, p_w2tlo, 1);
    convert_x_kernel<<<2048, 256>>>((const float4*)x);

    // scalar path: scales + lvp/lp
    finalize_all_kernel<<<1, 256>>>(b1, b2, w3mu, w3rho, b3mu, b3rho,
                                    lkw1, lkb1, lkw2, lkb2, out + (out_size - 2));

    // main path: two warp-MMA GEMMs + tiny layer 3
    dim3 grid(DIM / BN, MROWS / BM);   // (32, 8)
    gemm_kernel<<<grid, 256, SMEM_TOTAL>>>(p_xhi, p_xlo, p_w1thi, p_w1tlo, b1, 0, 0);
    gemm_kernel<<<grid, 256, SMEM_TOTAL>>>(p_h1hi, p_h1lo, p_w2thi, p_w2tlo, b2, 2, 1);
    layer3_kernel<<<128, 256>>>(w3mu, b3mu, out);
}

// round 5
// speedup vs baseline: 2.4934x; 1.1456x over previous
#include <cuda_runtime.h>
#include <cuda_bf16.h>
#include <math.h>
#include <stdint.h>

#define MROWS 1024
#define DIM   4096
#define NOUT  5
#define NHLOG2PI (-0.918938533204672741780329736406)
#define DPI 3.14159265358979323846

// GEMM tiling (warp-MMA, mma.sync m16n8k16 bf16)
#define BM 128
#define BN 128
#define BK 32
#define NCHUNK (DIM / BK)        // 128
#define ROWB 80                  // padded row bytes (32 bf16 = 64B data + 16B pad)
#define A_HI 0
#define A_LO (128 * ROWB)        // 10240
#define B_HI (2 * 128 * ROWB)    // 20480
#define B_LO (3 * 128 * ROWB)    // 30720
#define STAGE_BYTES (4 * 128 * ROWB)   // 40960
#define NSTAGE 3
#define SMEM_TOTAL (NSTAGE * STAGE_BYTES)   // 122880

// ---------------- scratch (device globals; no allocations allowed) ----------------
__device__ __nv_bfloat16 g_xhi[MROWS * DIM];
__device__ __nv_bfloat16 g_xlo[MROWS * DIM];
__device__ __nv_bfloat16 g_w1thi[DIM * DIM];
__device__ __nv_bfloat16 g_w1tlo[DIM * DIM];
__device__ __nv_bfloat16 g_w2thi[DIM * DIM];
__device__ __nv_bfloat16 g_w2tlo[DIM * DIM];
__device__ __nv_bfloat16 g_h1hi[MROWS * DIM];
__device__ __nv_bfloat16 g_h1lo[MROWS * DIM];
__device__ float  g_h2[MROWS * DIM];
__device__ double g_wpart[2][4096];
__device__ double g_spart[4][64];    // b1ss, b2ss, lvp3, lp3 partials
__device__ float  g_scales[4];       // 1/||w1||, 1/||b1||, 1/||w2||, 1/||b2||

// ---------------- PTX helpers ----------------
__device__ __forceinline__ uint32_t smem_u32(const void* p) {
    uint32_t a;
    asm("{ .reg .u64 t; cvta.to.shared.u64 t, %1; cvt.u32.u64 %0, t; }" : "=r"(a) : "l"(p));
    return a;
}
__device__ __forceinline__ void cpasync16(uint32_t dst, const void* src) {
    asm volatile("cp.async.cg.shared.global [%0], [%1], 16;" :: "r"(dst), "l"(src));
}
__device__ __forceinline__ void ldsm4(uint32_t& r0, uint32_t& r1, uint32_t& r2, uint32_t& r3,
                                      uint32_t addr) {
    asm volatile("ldmatrix.sync.aligned.m8n8.x4.shared.b16 {%0,%1,%2,%3}, [%4];"
                 : "=r"(r0), "=r"(r1), "=r"(r2), "=r"(r3) : "r"(addr));
}
__device__ __forceinline__ void mma_bf16(float* c, const uint32_t* a, const uint32_t* b) {
    asm volatile("mma.sync.aligned.m16n8k16.row.col.f32.bf16.bf16.f32 "
                 "{%0,%1,%2,%3}, {%4,%5,%6,%7}, {%8,%9}, {%0,%1,%2,%3};"
                 : "+f"(c[0]), "+f"(c[1]), "+f"(c[2]), "+f"(c[3])
                 : "r"(a[0]), "r"(a[1]), "r"(a[2]), "r"(a[3]), "r"(b[0]), "r"(b[1]));
}

// ---------------- block reduce (deterministic) ----------------
__device__ __forceinline__ double block_reduce_256(double v) {
    __shared__ double sm[256];
    int t = threadIdx.x + threadIdx.y * blockDim.x;
    sm[t] = v;
    __syncthreads();
    for (int s = 128; s > 0; s >>= 1) {
        if (t < s) sm[t] += sm[t + s];
        __syncthreads();
    }
    double r = sm[0];
    __syncthreads();
    return r;
}

// ---------------- weight convert: f32 [K][N] -> bf16 hi/lo transposed [N][K] + sumsq ----------------
// 64x64 tiles, bf162 coalesced transposed stores.
__global__ void convert_w_kernel(const float* __restrict__ W,
                                 __nv_bfloat16* __restrict__ Thi,
                                 __nv_bfloat16* __restrict__ Tlo,
                                 int slot) {
    __shared__ float tile[64][65];
    const int tx = threadIdx.x, ty = threadIdx.y;   // (32, 8)
    const int k0 = blockIdx.y * 64, n0 = blockIdx.x * 64;
    double ss = 0.0;
#pragma unroll
    for (int rr = 0; rr < 8; rr++) {
        const int kl = ty + rr * 8;
#pragma unroll
        for (int ch = 0; ch < 2; ch++) {
            const int nl = tx + ch * 32;
            float v = W[(size_t)(k0 + kl) * DIM + n0 + nl];
            tile[kl][nl] = v;
            ss += (double)v * (double)v;
        }
    }
    __syncthreads();
#pragma unroll
    for (int rr = 0; rr < 8; rr++) {
        const int nl = ty + rr * 8;
        const float v0 = tile[2 * tx][nl];
        const float v1 = tile[2 * tx + 1][nl];
        __nv_bfloat16 h0 = __float2bfloat16(v0);
        __nv_bfloat16 h1 = __float2bfloat16(v1);
        size_t o = (size_t)(n0 + nl) * DIM + k0 + 2 * tx;
        *(__nv_bfloat162*)(Thi + o) = __halves2bfloat162(h0, h1);
        *(__nv_bfloat162*)(Tlo + o) = __halves2bfloat162(
            __float2bfloat16(v0 - __bfloat162float(h0)),
            __float2bfloat16(v1 - __bfloat162float(h1)));
    }
    double r = block_reduce_256(ss);
    if (tx == 0 && ty == 0) g_wpart[slot][blockIdx.y * 64 + blockIdx.x] = r;
}

// ---------------- x convert: f32 -> bf16 hi/lo ----------------
__global__ void convert_x_kernel(const float4* __restrict__ x) {
    const int n4 = MROWS * DIM / 4;
    __nv_bfloat162* xh = (__nv_bfloat162*)g_xhi;
    __nv_bfloat162* xl = (__nv_bfloat162*)g_xlo;
    for (int i = blockIdx.x * blockDim.x + threadIdx.x; i < n4; i += gridDim.x * blockDim.x) {
        float4 v = x[i];
        __nv_bfloat16 h0 = __float2bfloat16(v.x), h1 = __float2bfloat16(v.y);
        __nv_bfloat16 h2 = __float2bfloat16(v.z), h3 = __float2bfloat16(v.w);
        xh[i * 2 + 0] = __halves2bfloat162(h0, h1);
        xh[i * 2 + 1] = __halves2bfloat162(h2, h3);
        xl[i * 2 + 0] = __halves2bfloat162(
            __float2bfloat16(v.x - __bfloat162float(h0)),
            __float2bfloat16(v.y - __bfloat162float(h1)));
        xl[i * 2 + 1] = __halves2bfloat162(
            __float2bfloat16(v.z - __bfloat162float(h2)),
            __float2bfloat16(v.w - __bfloat162float(h3)));
    }
}

// ---------------- parallel small partials ----------------
__global__ void small_partials_kernel(const float* __restrict__ b1, const float* __restrict__ b2,
                                      const float* __restrict__ w3mu, const float* __restrict__ w3rho,
                                      const float* __restrict__ b3mu, const float* __restrict__ b3rho) {
    const int t = threadIdx.x;
    const int g = blockIdx.x * 256 + t;
    const int stride = 64 * 256;   // 16384
    double a;

    a = 0.0;
    for (int i = g; i < DIM; i += stride) { double x = (double)b1[i]; a += x * x; }
    { double r = block_reduce_256(a); if (t == 0) g_spart[0][blockIdx.x] = r; }

    a = 0.0;
    for (int i = g; i < DIM; i += stride) { double x = (double)b2[i]; a += x * x; }
    { double r = block_reduce_256(a); if (t == 0) g_spart[1][blockIdx.x] = r; }

    a = 0.0;
    for (int i = g; i < NOUT * DIM; i += stride) {
        float r = w3rho[i];
        a += (double)(-0.918938533f - logf(log1pf(expf(r))));
    }
    for (int i = g; i < NOUT; i += stride) {
        float r = b3rho[i];
        a += (double)(-0.918938533f - logf(log1pf(expf(r))));
    }
    { double r = block_reduce_256(a); if (t == 0) g_spart[2][blockIdx.x] = r; }

    a = 0.0;
    for (int i = g; i < NOUT * DIM; i += stride) {
        float m = w3mu[i];
        a += (double)(-0.918938533f - 0.5f * m * m);
    }
    for (int i = g; i < NOUT; i += stride) {
        float m = b3mu[i];
        a += (double)(-0.918938533f - 0.5f * m * m);
    }
    { double r = block_reduce_256(a); if (t == 0) g_spart[3][blockIdx.x] = r; }
}

// ---------------- scalar math ----------------
__device__ double log_C_vmf(double d, double kappa) {
    double s  = 0.5 * d - 1.0;
    double x  = kappa / s;
    double sq = sqrt(1.0 + x * x);
    double eta = sq + log(x) - log1p(sq);
    double lbi = s * eta - 0.5 * log(2.0 * DPI * s) - 0.5 * log(sq);
    return d * NHLOG2PI + s * log(kappa) - lbi;
}
__device__ double log_surf(double d) {
    double h = 0.5 * (d + 1.0);
    return log(2.0) + h * log(DPI) - lgamma(h);
}

// ---------------- finalize: reduce partials + scales + lvp/lp ----------------
__global__ void finalize_kernel(const float* __restrict__ lkw1, const float* __restrict__ lkb1,
                                const float* __restrict__ lkw2, const float* __restrict__ lkb2,
                                float* __restrict__ out_scalars) {
    const int t = threadIdx.x;
    double a;

    a = 0.0; for (int i = t; i < 4096; i += 256) a += g_wpart[0][i];
    double sw1 = block_reduce_256(a);
    a = 0.0; for (int i = t; i < 4096; i += 256) a += g_wpart[1][i];
    double sw2 = block_reduce_256(a);
    a = (t < 64) ? g_spart[0][t] : 0.0;
    double sb1 = block_reduce_256(a);
    a = (t < 64) ? g_spart[1][t] : 0.0;
    double sb2 = block_reduce_256(a);
    a = (t < 64) ? g_spart[2][t] : 0.0;
    double lvp3 = block_reduce_256(a);
    a = (t < 64) ? g_spart[3][t] : 0.0;
    double lp3 = block_reduce_256(a);

    if (t == 0) {
        g_scales[0] = (float)(1.0 / sqrt(sw1));
        g_scales[1] = (float)(1.0 / sqrt(sb1));
        g_scales[2] = (float)(1.0 / sqrt(sw2));
        g_scales[3] = (float)(1.0 / sqrt(sb2));

        double kw1 = exp((double)lkw1[0]) + 1e-6;
        double kb1 = exp((double)lkb1[0]) + 1e-6;
        double kw2 = exp((double)lkw2[0]) + 1e-6;
        double kb2 = exp((double)lkb2[0]) + 1e-6;
        double dw = (double)DIM * (double)DIM;
        double db = (double)DIM;

        double lvp = kw1 + log_C_vmf(dw, kw1) + kb1 + log_C_vmf(db, kb1)
                   + kw2 + log_C_vmf(dw, kw2) + kb2 + log_C_vmf(db, kb2) + lvp3;
        double lp = -4.0 * log_surf(dw) + lp3;   // source bug preserved (all terms use d_w)

        out_scalars[0] = (float)lvp;
        out_scalars[1] = (float)lp;
    }
}

// ---------------- warp-MMA GEMM: C = relu((A @ B^T)*invw + bias*invb) ----------------
__device__ __forceinline__ void load_stage(uint32_t base,
                                           const __nv_bfloat16* __restrict__ Ahi,
                                           const __nv_bfloat16* __restrict__ Alo,
                                           const __nv_bfloat16* __restrict__ Bhi,
                                           const __nv_bfloat16* __restrict__ Blo,
                                           int m0, int n0, int k0, int tid) {
#pragma unroll
    for (int q = 0; q < 2; q++) {
        int c = tid + q * 256;
        int row = c >> 2, c16 = c & 3;
        uint32_t off = (uint32_t)(row * ROWB + c16 * 16);
        size_t asrc = (size_t)(m0 + row) * DIM + k0 + c16 * 8;
        size_t bsrc = (size_t)(n0 + row) * DIM + k0 + c16 * 8;
        cpasync16(base + A_HI + off, Ahi + asrc);
        cpasync16(base + A_LO + off, Alo + asrc);
        cpasync16(base + B_HI + off, Bhi + bsrc);
        cpasync16(base + B_LO + off, Blo + bsrc);
    }
}

__global__ void __launch_bounds__(256)
gemm_kernel(const __nv_bfloat16* __restrict__ Ahi, const __nv_bfloat16* __restrict__ Alo,
            const __nv_bfloat16* __restrict__ Bhi, const __nv_bfloat16* __restrict__ Blo,
            const float* __restrict__ bias, int sidx, int mode) {
    extern __shared__ char smem[];
    const uint32_t sb = smem_u32(smem);
    const int tid = threadIdx.x, wid = tid >> 5, lane = tid & 31;
    const int wm = wid >> 2, wn = wid & 3;     // 2 x 4 warp grid
    const int m0 = blockIdx.y * BM, n0 = blockIdx.x * BN;

    float acc[4][4][4];
#pragma unroll
    for (int i = 0; i < 4; i++)
#pragma unroll
        for (int j = 0; j < 4; j++)
#pragma unroll
            for (int k = 0; k < 4; k++) acc[i][j][k] = 0.0f;

    const uint32_t a_row = (uint32_t)(wm * 64 + (lane & 15));
    const uint32_t a_colh = (uint32_t)(lane >> 4);
    const uint32_t b_row = (uint32_t)(wn * 32 + ((lane >> 4) & 1) * 8 + (lane & 7));
    const uint32_t b_colh = (uint32_t)((lane >> 3) & 1);

    // prologue: stages 0 and 1
    load_stage(sb, Ahi, Alo, Bhi, Blo, m0, n0, 0, tid);
    asm volatile("cp.async.commit_group;" ::: "memory");
    load_stage(sb + STAGE_BYTES, Ahi, Alo, Bhi, Blo, m0, n0, BK, tid);
    asm volatile("cp.async.commit_group;" ::: "memory");

    for (int i = 0; i < NCHUNK; i++) {
        const uint32_t stg = sb + (uint32_t)(i % NSTAGE) * STAGE_BYTES;
        if (i + 1 < NCHUNK) {
            asm volatile("cp.async.wait_group 1;" ::: "memory");
        } else {
            asm volatile("cp.async.wait_group 0;" ::: "memory");
        }
        __syncthreads();
        if (i + 2 < NCHUNK) {
            load_stage(sb + (uint32_t)((i + 2) % NSTAGE) * STAGE_BYTES,
                       Ahi, Alo, Bhi, Blo, m0, n0, (i + 2) * BK, tid);
            asm volatile("cp.async.commit_group;" ::: "memory");
        }

#pragma unroll
        for (int ks = 0; ks < 2; ks++) {
            const uint32_t acol = (uint32_t)(ks * 2 + a_colh) * 16;
            const uint32_t bcol = (uint32_t)(ks * 2 + b_colh) * 16;

            uint32_t ah[4][4], bh[2][4];
#pragma unroll
            for (int mt = 0; mt < 4; mt++)
                ldsm4(ah[mt][0], ah[mt][1], ah[mt][2], ah[mt][3],
                      stg + A_HI + (a_row + mt * 16) * ROWB + acol);
#pragma unroll
            for (int p = 0; p < 2; p++)
                ldsm4(bh[p][0], bh[p][1], bh[p][2], bh[p][3],
                      stg + B_HI + (b_row + p * 16) * ROWB + bcol);

#pragma unroll
            for (int mt = 0; mt < 4; mt++)
#pragma unroll
                for (int nt = 0; nt < 4; nt++)
                    mma_bf16(acc[mt][nt], ah[mt], &bh[nt >> 1][(nt & 1) * 2]);

            {
                uint32_t bl[2][4];
#pragma unroll
                for (int p = 0; p < 2; p++)
                    ldsm4(bl[p][0], bl[p][1], bl[p][2], bl[p][3],
                          stg + B_LO + (b_row + p * 16) * ROWB + bcol);
#pragma unroll
                for (int mt = 0; mt < 4; mt++)
#pragma unroll
                    for (int nt = 0; nt < 4; nt++)
                        mma_bf16(acc[mt][nt], ah[mt], &bl[nt >> 1][(nt & 1) * 2]);
            }
            {
                uint32_t al[4][4];
#pragma unroll
                for (int mt = 0; mt < 4; mt++)
                    ldsm4(al[mt][0], al[mt][1], al[mt][2], al[mt][3],
                          stg + A_LO + (a_row + mt * 16) * ROWB + acol);
#pragma unroll
                for (int mt = 0; mt < 4; mt++)
#pragma unroll
                    for (int nt = 0; nt < 4; nt++)
                        mma_bf16(acc[mt][nt], al[mt], &bh[nt >> 1][(nt & 1) * 2]);
            }
        }
    }

    // ------- epilogue: scale + bias + relu; direct fragment stores -------
    const float invw = g_scales[sidx];
    const float invb = g_scales[sidx + 1];
#pragma unroll
    for (int mt = 0; mt < 4; mt++) {
        const int r0 = m0 + wm * 64 + mt * 16 + (lane >> 2);
#pragma unroll
        for (int nt = 0; nt < 4; nt++) {
            const int col = n0 + wn * 32 + nt * 8 + 2 * (lane & 3);
            const float bv0 = bias[col] * invb;
            const float bv1 = bias[col + 1] * invb;
            float v00 = fmaxf(acc[mt][nt][0] * invw + bv0, 0.0f);
            float v01 = fmaxf(acc[mt][nt][1] * invw + bv1, 0.0f);
            float v10 = fmaxf(acc[mt][nt][2] * invw + bv0, 0.0f);
            float v11 = fmaxf(acc[mt][nt][3] * invw + bv1, 0.0f);
            const size_t o0 = (size_t)r0 * DIM + col;
            const size_t o1 = (size_t)(r0 + 8) * DIM + col;
            if (mode == 0) {
                __nv_bfloat16 h00 = __float2bfloat16(v00), h01 = __float2bfloat16(v01);
                __nv_bfloat16 h10 = __float2bfloat16(v10), h11 = __float2bfloat16(v11);
                *(__nv_bfloat162*)(g_h1hi + o0) = __halves2bfloat162(h00, h01);
                *(__nv_bfloat162*)(g_h1hi + o1) = __halves2bfloat162(h10, h11);
                *(__nv_bfloat162*)(g_h1lo + o0) = __halves2bfloat162(
                    __float2bfloat16(v00 - __bfloat162float(h00)),
                    __float2bfloat16(v01 - __bfloat162float(h01)));
                *(__nv_bfloat162*)(g_h1lo + o1) = __halves2bfloat162(
                    __float2bfloat16(v10 - __bfloat162float(h10)),
                    __float2bfloat16(v11 - __bfloat162float(h11)));
            } else {
                *(float2*)(g_h2 + o0) = make_float2(v00, v01);
                *(float2*)(g_h2 + o1) = make_float2(v10, v11);
            }
        }
    }
}

// ---------------- layer 3 (tiny GEMM) + log_softmax, one warp per row ----------------
__global__ void layer3_kernel(const float* __restrict__ w3,
                              const float* __restrict__ b3,
                              float* __restrict__ out) {
    const int warp = threadIdx.x >> 5;
    const int lane = threadIdx.x & 31;
    const int row = blockIdx.x * (blockDim.x >> 5) + warp;
    if (row >= MROWS) return;

    float acc[NOUT] = {0.f, 0.f, 0.f, 0.f, 0.f};
    const float* hrow = g_h2 + (size_t)row * DIM;
    for (int k = lane; k < DIM; k += 32) {
        float h = hrow[k];
#pragma unroll
        for (int o = 0; o < NOUT; o++) acc[o] += h * w3[o * DIM + k];
    }
#pragma unroll
    for (int o = 0; o < NOUT; o++)
#pragma unroll
        for (int off = 16; off > 0; off >>= 1)
            acc[o] += __shfl_xor_sync(0xffffffffu, acc[o], off);

    if (lane == 0) {
        float y[NOUT];
        float m = -1e30f;
#pragma unroll
        for (int o = 0; o < NOUT; o++) {
            y[o] = acc[o] + b3[o];
            m = fmaxf(m, y[o]);
        }
        float s = 0.0f;
#pragma unroll
        for (int o = 0; o < NOUT; o++) s += expf(y[o] - m);
        float lse = m + logf(s);
#pragma unroll
        for (int o = 0; o < NOUT; o++) out[row * NOUT + o] = y[o] - lse;
    }
}

// ---------------- launch ----------------
extern "C" void kernel_launch(void* const* d_in, const int* in_sizes, int n_in,
                              void* d_out, int out_size) {
    const float* x     = (const float*)d_in[0];
    const float* w1    = (const float*)d_in[1];
    const float* lkw1  = (const float*)d_in[2];
    const float* b1    = (const float*)d_in[3];
    const float* lkb1  = (const float*)d_in[4];
    const float* w2    = (const float*)d_in[5];
    const float* lkw2  = (const float*)d_in[6];
    const float* b2    = (const float*)d_in[7];
    const float* lkb2  = (const float*)d_in[8];
    const float* w3mu  = (const float*)d_in[9];
    const float* w3rho = (const float*)d_in[10];
    const float* b3mu  = (const float*)d_in[11];
    const float* b3rho = (const float*)d_in[12];
    float* out = (float*)d_out;

    static bool attr_done = false;
    if (!attr_done) {
        cudaFuncSetAttribute(gemm_kernel, cudaFuncAttributeMaxDynamicSharedMemorySize, SMEM_TOTAL);
        attr_done = true;
    }

    __nv_bfloat16 *p_xhi, *p_xlo, *p_w1thi, *p_w1tlo, *p_w2thi, *p_w2tlo, *p_h1hi, *p_h1lo;
    cudaGetSymbolAddress((void**)&p_xhi,  g_xhi);
    cudaGetSymbolAddress((void**)&p_xlo,  g_xlo);
    cudaGetSymbolAddress((void**)&p_w1thi, g_w1thi);
    cudaGetSymbolAddress((void**)&p_w1tlo, g_w1tlo);
    cudaGetSymbolAddress((void**)&p_w2thi, g_w2thi);
    cudaGetSymbolAddress((void**)&p_w2tlo, g_w2tlo);
    cudaGetSymbolAddress((void**)&p_h1hi, g_h1hi);
    cudaGetSymbolAddress((void**)&p_h1lo, g_h1lo);

    // 1-3: conversions (w-conversion fuses sumsq partials; 64x64 tiles)
    dim3 cgrid(DIM / 64, DIM / 64), cblk(32, 8);
    convert_w_kernel<<<cgrid, cblk>>>(w1, p_w1thi, p_w1tlo, 0);
    convert_w_kernel<<<cgrid, cblk>>>(w2, p_w2thi, p_w2tlo, 1);
    convert_x_kernel<<<2048, 256>>>((const float4*)x);

    // 4-5: scalar path (parallel partials + tiny finalize)
    small_partials_kernel<<<64, 256>>>(b1, b2, w3mu, w3rho, b3mu, b3rho);
    finalize_kernel<<<1, 256>>>(lkw1, lkb1, lkw2, lkb2, out + (out_size - 2));

    // 6-8: two warp-MMA GEMMs + tiny layer 3 (launch #6 = gemm1 for ncu -s 5)
    dim3 grid(DIM / BN, MROWS / BM);   // (32, 8)
    gemm_kernel<<<grid, 256, SMEM_TOTAL>>>(p_xhi, p_xlo, p_w1thi, p_w1tlo, b1, 0, 0);
    gemm_kernel<<<grid, 256, SMEM_TOTAL>>>(p_h1hi, p_h1lo, p_w2thi, p_w2tlo, b2, 2, 1);
    layer3_kernel<<<128, 256>>>(w3mu, b3mu, out);
}

// round 6
// speedup vs baseline: 4.4844x; 1.7985x over previous
#include <cuda_runtime.h>
#include <cuda_bf16.h>
#include <math.h>
#include <stdint.h>

#define MROWS 1024
#define DIM   4096
#define NOUT  5
#define NHLOG2PI (-0.918938533204672741780329736406)
#define DPI 3.14159265358979323846

// GEMM tiling (warp-MMA, mma.sync m16n8k16 bf16, single split)
#define BM 128
#define BN 256
#define BK 32
#define NCHUNK (DIM / BK)        // 128
#define ROWB 80                  // padded row bytes (32 bf16 = 64B data + 16B pad)
#define A_OFF 0
#define B_OFF (128 * ROWB)              // 10240
#define STAGE_BYTES (B_OFF + 256 * ROWB) // 30720
#define NSTAGE 4
#define SMEM_TOTAL (NSTAGE * STAGE_BYTES)   // 122880

// ---------------- scratch (device globals; no allocations allowed) ----------------
__device__ __nv_bfloat16 g_xb[MROWS * DIM];
__device__ __nv_bfloat16 g_w1t[DIM * DIM];
__device__ __nv_bfloat16 g_w2t[DIM * DIM];
__device__ __nv_bfloat16 g_h1[MROWS * DIM];
__device__ float  g_h2[MROWS * DIM];
__device__ double g_wpart[2][4096];
__device__ double g_spart[4][64];    // b1ss, b2ss, lvp3, lp3 partials
__device__ float  g_scales[4];       // 1/||w1||, 1/||b1||, 1/||w2||, 1/||b2||

// ---------------- PTX helpers ----------------
__device__ __forceinline__ uint32_t smem_u32(const void* p) {
    uint32_t a;
    asm("{ .reg .u64 t; cvta.to.shared.u64 t, %1; cvt.u32.u64 %0, t; }" : "=r"(a) : "l"(p));
    return a;
}
__device__ __forceinline__ void cpasync16(uint32_t dst, const void* src) {
    asm volatile("cp.async.cg.shared.global [%0], [%1], 16;" :: "r"(dst), "l"(src));
}
__device__ __forceinline__ void ldsm4(uint32_t& r0, uint32_t& r1, uint32_t& r2, uint32_t& r3,
                                      uint32_t addr) {
    asm volatile("ldmatrix.sync.aligned.m8n8.x4.shared.b16 {%0,%1,%2,%3}, [%4];"
                 : "=r"(r0), "=r"(r1), "=r"(r2), "=r"(r3) : "r"(addr));
}
__device__ __forceinline__ void mma_bf16(float* c, const uint32_t* a, const uint32_t* b) {
    asm volatile("mma.sync.aligned.m16n8k16.row.col.f32.bf16.bf16.f32 "
                 "{%0,%1,%2,%3}, {%4,%5,%6,%7}, {%8,%9}, {%0,%1,%2,%3};"
                 : "+f"(c[0]), "+f"(c[1]), "+f"(c[2]), "+f"(c[3])
                 : "r"(a[0]), "r"(a[1]), "r"(a[2]), "r"(a[3]), "r"(b[0]), "r"(b[1]));
}

// ---------------- block reduce (deterministic) ----------------
__device__ __forceinline__ double block_reduce_256(double v) {
    __shared__ double sm[256];
    int t = threadIdx.x + threadIdx.y * blockDim.x;
    sm[t] = v;
    __syncthreads();
    for (int s = 128; s > 0; s >>= 1) {
        if (t < s) sm[t] += sm[t + s];
        __syncthreads();
    }
    double r = sm[0];
    __syncthreads();
    return r;
}

// ---------------- weight convert: f32 [K][N] -> bf16 transposed [N][K] + sumsq ----------------
__global__ void convert_w_kernel(const float* __restrict__ W,
                                 __nv_bfloat16* __restrict__ T,
                                 int slot) {
    __shared__ float tile[64][65];
    const int tx = threadIdx.x, ty = threadIdx.y;   // (32, 8)
    const int k0 = blockIdx.y * 64, n0 = blockIdx.x * 64;
    double ss = 0.0;
#pragma unroll
    for (int rr = 0; rr < 8; rr++) {
        const int kl = ty + rr * 8;
#pragma unroll
        for (int ch = 0; ch < 2; ch++) {
            const int nl = tx + ch * 32;
            float v = W[(size_t)(k0 + kl) * DIM + n0 + nl];
            tile[kl][nl] = v;
            ss += (double)v * (double)v;
        }
    }
    __syncthreads();
#pragma unroll
    for (int rr = 0; rr < 8; rr++) {
        const int nl = ty + rr * 8;
        size_t o = (size_t)(n0 + nl) * DIM + k0 + 2 * tx;
        *(__nv_bfloat162*)(T + o) = __halves2bfloat162(
            __float2bfloat16(tile[2 * tx][nl]),
            __float2bfloat16(tile[2 * tx + 1][nl]));
    }
    double r = block_reduce_256(ss);
    if (tx == 0 && ty == 0) g_wpart[slot][blockIdx.y * 64 + blockIdx.x] = r;
}

// ---------------- x convert: f32 -> bf16 ----------------
__global__ void convert_x_kernel(const float4* __restrict__ x) {
    const int n4 = MROWS * DIM / 4;
    __nv_bfloat162* xb = (__nv_bfloat162*)g_xb;
    for (int i = blockIdx.x * blockDim.x + threadIdx.x; i < n4; i += gridDim.x * blockDim.x) {
        float4 v = x[i];
        xb[i * 2 + 0] = __halves2bfloat162(__float2bfloat16(v.x), __float2bfloat16(v.y));
        xb[i * 2 + 1] = __halves2bfloat162(__float2bfloat16(v.z), __float2bfloat16(v.w));
    }
}

// ---------------- parallel small partials ----------------
__global__ void small_partials_kernel(const float* __restrict__ b1, const float* __restrict__ b2,
                                      const float* __restrict__ w3mu, const float* __restrict__ w3rho,
                                      const float* __restrict__ b3mu, const float* __restrict__ b3rho) {
    const int t = threadIdx.x;
    const int g = blockIdx.x * 256 + t;
    const int stride = 64 * 256;
    double a;

    a = 0.0;
    for (int i = g; i < DIM; i += stride) { double x = (double)b1[i]; a += x * x; }
    { double r = block_reduce_256(a); if (t == 0) g_spart[0][blockIdx.x] = r; }

    a = 0.0;
    for (int i = g; i < DIM; i += stride) { double x = (double)b2[i]; a += x * x; }
    { double r = block_reduce_256(a); if (t == 0) g_spart[1][blockIdx.x] = r; }

    a = 0.0;
    for (int i = g; i < NOUT * DIM; i += stride) {
        float r = w3rho[i];
        a += (double)(-0.918938533f - logf(log1pf(expf(r))));
    }
    for (int i = g; i < NOUT; i += stride) {
        float r = b3rho[i];
        a += (double)(-0.918938533f - logf(log1pf(expf(r))));
    }
    { double r = block_reduce_256(a); if (t == 0) g_spart[2][blockIdx.x] = r; }

    a = 0.0;
    for (int i = g; i < NOUT * DIM; i += stride) {
        float m = w3mu[i];
        a += (double)(-0.918938533f - 0.5f * m * m);
    }
    for (int i = g; i < NOUT; i += stride) {
        float m = b3mu[i];
        a += (double)(-0.918938533f - 0.5f * m * m);
    }
    { double r = block_reduce_256(a); if (t == 0) g_spart[3][blockIdx.x] = r; }
}

// ---------------- scalar math ----------------
__device__ double log_C_vmf(double d, double kappa) {
    double s  = 0.5 * d - 1.0;
    double x  = kappa / s;
    double sq = sqrt(1.0 + x * x);
    double eta = sq + log(x) - log1p(sq);
    double lbi = s * eta - 0.5 * log(2.0 * DPI * s) - 0.5 * log(sq);
    return d * NHLOG2PI + s * log(kappa) - lbi;
}
__device__ double log_surf(double d) {
    double h = 0.5 * (d + 1.0);
    return log(2.0) + h * log(DPI) - lgamma(h);
}

// ---------------- finalize: reduce partials + scales + lvp/lp ----------------
__global__ void finalize_kernel(const float* __restrict__ lkw1, const float* __restrict__ lkb1,
                                const float* __restrict__ lkw2, const float* __restrict__ lkb2,
                                float* __restrict__ out_scalars) {
    const int t = threadIdx.x;
    double a;

    a = 0.0; for (int i = t; i < 4096; i += 256) a += g_wpart[0][i];
    double sw1 = block_reduce_256(a);
    a = 0.0; for (int i = t; i < 4096; i += 256) a += g_wpart[1][i];
    double sw2 = block_reduce_256(a);
    a = (t < 64) ? g_spart[0][t] : 0.0;
    double sb1 = block_reduce_256(a);
    a = (t < 64) ? g_spart[1][t] : 0.0;
    double sb2 = block_reduce_256(a);
    a = (t < 64) ? g_spart[2][t] : 0.0;
    double lvp3 = block_reduce_256(a);
    a = (t < 64) ? g_spart[3][t] : 0.0;
    double lp3 = block_reduce_256(a);

    if (t == 0) {
        g_scales[0] = (float)(1.0 / sqrt(sw1));
        g_scales[1] = (float)(1.0 / sqrt(sb1));
        g_scales[2] = (float)(1.0 / sqrt(sw2));
        g_scales[3] = (float)(1.0 / sqrt(sb2));

        double kw1 = exp((double)lkw1[0]) + 1e-6;
        double kb1 = exp((double)lkb1[0]) + 1e-6;
        double kw2 = exp((double)lkw2[0]) + 1e-6;
        double kb2 = exp((double)lkb2[0]) + 1e-6;
        double dw = (double)DIM * (double)DIM;
        double db = (double)DIM;

        double lvp = kw1 + log_C_vmf(dw, kw1) + kb1 + log_C_vmf(db, kb1)
                   + kw2 + log_C_vmf(dw, kw2) + kb2 + log_C_vmf(db, kb2) + lvp3;
        double lp = -4.0 * log_surf(dw) + lp3;   // source bug preserved (all terms use d_w)

        out_scalars[0] = (float)lvp;
        out_scalars[1] = (float)lp;
    }
}

// ---------------- warp-MMA GEMM: C = relu((A @ B^T)*invw + bias*invb) ----------------
// A: [M][K] bf16 (K-major). B: [N][K] bf16 (K-major, pre-transposed weights).
__device__ __forceinline__ void load_stage(uint32_t base,
                                           const __nv_bfloat16* __restrict__ A,
                                           const __nv_bfloat16* __restrict__ B,
                                           int m0, int n0, int k0, int tid) {
#pragma unroll
    for (int q = 0; q < 2; q++) {
        int c = tid + q * 256;                 // 0..511
        int row = c >> 2, c16 = c & 3;
        uint32_t off = (uint32_t)(row * ROWB + c16 * 16);
        cpasync16(base + A_OFF + off, A + (size_t)(m0 + row) * DIM + k0 + c16 * 8);
    }
#pragma unroll
    for (int q = 0; q < 4; q++) {
        int c = tid + q * 256;                 // 0..1023
        int row = c >> 2, c16 = c & 3;
        uint32_t off = (uint32_t)(row * ROWB + c16 * 16);
        cpasync16(base + B_OFF + off, B + (size_t)(n0 + row) * DIM + k0 + c16 * 8);
    }
}

__global__ void __launch_bounds__(256)
gemm_kernel(const __nv_bfloat16* __restrict__ A, const __nv_bfloat16* __restrict__ B,
            const float* __restrict__ bias, int sidx, int mode) {
    extern __shared__ char smem[];
    const uint32_t sb = smem_u32(smem);
    const int tid = threadIdx.x, wid = tid >> 5, lane = tid & 31;
    const int wm = wid >> 2, wn = wid & 3;     // 2 x 4 warp grid; warp tile 64x64
    const int m0 = blockIdx.y * BM, n0 = blockIdx.x * BN;

    float acc[4][8][4];
#pragma unroll
    for (int i = 0; i < 4; i++)
#pragma unroll
        for (int j = 0; j < 8; j++)
#pragma unroll
            for (int k = 0; k < 4; k++) acc[i][j][k] = 0.0f;

    const uint32_t a_row = (uint32_t)(wm * 64 + (lane & 15));
    const uint32_t a_colh = (uint32_t)(lane >> 4);
    const uint32_t b_row = (uint32_t)(wn * 64 + ((lane >> 4) & 1) * 8 + (lane & 7));
    const uint32_t b_colh = (uint32_t)((lane >> 3) & 1);

    // prologue: stages 0..2
    load_stage(sb + 0 * STAGE_BYTES, A, B, m0, n0, 0 * BK, tid);
    asm volatile("cp.async.commit_group;" ::: "memory");
    load_stage(sb + 1 * STAGE_BYTES, A, B, m0, n0, 1 * BK, tid);
    asm volatile("cp.async.commit_group;" ::: "memory");
    load_stage(sb + 2 * STAGE_BYTES, A, B, m0, n0, 2 * BK, tid);
    asm volatile("cp.async.commit_group;" ::: "memory");

    for (int i = 0; i < NCHUNK; i++) {
        const uint32_t stg = sb + (uint32_t)(i % NSTAGE) * STAGE_BYTES;
        if (i <= NCHUNK - 3) {
            asm volatile("cp.async.wait_group 2;" ::: "memory");
        } else if (i == NCHUNK - 2) {
            asm volatile("cp.async.wait_group 1;" ::: "memory");
        } else {
            asm volatile("cp.async.wait_group 0;" ::: "memory");
        }
        __syncthreads();
        if (i + 3 < NCHUNK) {
            load_stage(sb + (uint32_t)((i + 3) % NSTAGE) * STAGE_BYTES,
                       A, B, m0, n0, (i + 3) * BK, tid);
            asm volatile("cp.async.commit_group;" ::: "memory");
        }

#pragma unroll
        for (int ks = 0; ks < 2; ks++) {
            const uint32_t acol = (uint32_t)(ks * 2 + a_colh) * 16;
            const uint32_t bcol = (uint32_t)(ks * 2 + b_colh) * 16;

            uint32_t ah[4][4], bh[4][4];
#pragma unroll
            for (int mt = 0; mt < 4; mt++)
                ldsm4(ah[mt][0], ah[mt][1], ah[mt][2], ah[mt][3],
                      stg + A_OFF + (a_row + mt * 16) * ROWB + acol);
#pragma unroll
            for (int p = 0; p < 4; p++)
                ldsm4(bh[p][0], bh[p][1], bh[p][2], bh[p][3],
                      stg + B_OFF + (b_row + p * 16) * ROWB + bcol);

#pragma unroll
            for (int mt = 0; mt < 4; mt++)
#pragma unroll
                for (int nt = 0; nt < 8; nt++)
                    mma_bf16(acc[mt][nt], ah[mt], &bh[nt >> 1][(nt & 1) * 2]);
        }
    }

    // ------- epilogue: scale + bias + relu; direct fragment stores -------
    const float invw = g_scales[sidx];
    const float invb = g_scales[sidx + 1];
#pragma unroll
    for (int mt = 0; mt < 4; mt++) {
        const int r0 = m0 + wm * 64 + mt * 16 + (lane >> 2);
#pragma unroll
        for (int nt = 0; nt < 8; nt++) {
            const int col = n0 + wn * 64 + nt * 8 + 2 * (lane & 3);
            const float bv0 = bias[col] * invb;
            const float bv1 = bias[col + 1] * invb;
            float v00 = fmaxf(acc[mt][nt][0] * invw + bv0, 0.0f);
            float v01 = fmaxf(acc[mt][nt][1] * invw + bv1, 0.0f);
            float v10 = fmaxf(acc[mt][nt][2] * invw + bv0, 0.0f);
            float v11 = fmaxf(acc[mt][nt][3] * invw + bv1, 0.0f);
            const size_t o0 = (size_t)r0 * DIM + col;
            const size_t o1 = (size_t)(r0 + 8) * DIM + col;
            if (mode == 0) {
                *(__nv_bfloat162*)(g_h1 + o0) =
                    __halves2bfloat162(__float2bfloat16(v00), __float2bfloat16(v01));
                *(__nv_bfloat162*)(g_h1 + o1) =
                    __halves2bfloat162(__float2bfloat16(v10), __float2bfloat16(v11));
            } else {
                *(float2*)(g_h2 + o0) = make_float2(v00, v01);
                *(float2*)(g_h2 + o1) = make_float2(v10, v11);
            }
        }
    }
}

// ---------------- layer 3 (tiny GEMM) + log_softmax, one warp per row ----------------
__global__ void layer3_kernel(const float* __restrict__ w3,
                              const float* __restrict__ b3,
                              float* __restrict__ out) {
    const int warp = threadIdx.x >> 5;
    const int lane = threadIdx.x & 31;
    const int row = blockIdx.x * (blockDim.x >> 5) + warp;
    if (row >= MROWS) return;

    float acc[NOUT] = {0.f, 0.f, 0.f, 0.f, 0.f};
    const float* hrow = g_h2 + (size_t)row * DIM;
    for (int k = lane; k < DIM; k += 32) {
        float h = hrow[k];
#pragma unroll
        for (int o = 0; o < NOUT; o++) acc[o] += h * w3[o * DIM + k];
    }
#pragma unroll
    for (int o = 0; o < NOUT; o++)
#pragma unroll
        for (int off = 16; off > 0; off >>= 1)
            acc[o] += __shfl_xor_sync(0xffffffffu, acc[o], off);

    if (lane == 0) {
        float y[NOUT];
        float m = -1e30f;
#pragma unroll
        for (int o = 0; o < NOUT; o++) {
            y[o] = acc[o] + b3[o];
            m = fmaxf(m, y[o]);
        }
        float s = 0.0f;
#pragma unroll
        for (int o = 0; o < NOUT; o++) s += expf(y[o] - m);
        float lse = m + logf(s);
#pragma unroll
        for (int o = 0; o < NOUT; o++) out[row * NOUT + o] = y[o] - lse;
    }
}

// ---------------- launch ----------------
extern "C" void kernel_launch(void* const* d_in, const int* in_sizes, int n_in,
                              void* d_out, int out_size) {
    const float* x     = (const float*)d_in[0];
    const float* w1    = (const float*)d_in[1];
    const float* lkw1  = (const float*)d_in[2];
    const float* b1    = (const float*)d_in[3];
    const float* lkb1  = (const float*)d_in[4];
    const float* w2    = (const float*)d_in[5];
    const float* lkw2  = (const float*)d_in[6];
    const float* b2    = (const float*)d_in[7];
    const float* lkb2  = (const float*)d_in[8];
    const float* w3mu  = (const float*)d_in[9];
    const float* w3rho = (const float*)d_in[10];
    const float* b3mu  = (const float*)d_in[11];
    const float* b3rho = (const float*)d_in[12];
    float* out = (float*)d_out;

    static bool attr_done = false;
    if (!attr_done) {
        cudaFuncSetAttribute(gemm_kernel, cudaFuncAttributeMaxDynamicSharedMemorySize, SMEM_TOTAL);
        attr_done = true;
    }

    __nv_bfloat16 *p_xb, *p_w1t, *p_w2t, *p_h1;
    cudaGetSymbolAddress((void**)&p_xb,  g_xb);
    cudaGetSymbolAddress((void**)&p_w1t, g_w1t);
    cudaGetSymbolAddress((void**)&p_w2t, g_w2t);
    cudaGetSymbolAddress((void**)&p_h1,  g_h1);

    // conversions (w-conversion fuses sumsq partials; 64x64 tiles)
    dim3 cgrid(DIM / 64, DIM / 64), cblk(32, 8);
    convert_w_kernel<<<cgrid, cblk>>>(w1, p_w1t, 0);
    convert_w_kernel<<<cgrid, cblk>>>(w2, p_w2t, 1);
    convert_x_kernel<<<2048, 256>>>((const float4*)x);

    // scalar path
    small_partials_kernel<<<64, 256>>>(b1, b2, w3mu, w3rho, b3mu, b3rho);
    finalize_kernel<<<1, 256>>>(lkw1, lkb1, lkw2, lkb2, out + (out_size - 2));

    // two warp-MMA GEMMs + tiny layer 3
    dim3 grid(DIM / BN, MROWS / BM);   // (16, 8) = 128 CTAs
    gemm_kernel<<<grid, 256, SMEM_TOTAL>>>(p_xb,  p_w1t, b1, 0, 0);
    gemm_kernel<<<grid, 256, SMEM_TOTAL>>>(p_h1, p_w2t, b2, 2, 1);
    layer3_kernel<<<128, 256>>>(w3mu, b3mu, out);
}

// round 7
// speedup vs baseline: 5.0525x; 1.1267x over previous
#include <cuda_runtime.h>
#include <cuda_bf16.h>
#include <math.h>
#include <stdint.h>

#define MROWS 1024
#define DIM   4096
#define NOUT  5
#define NHLOG2PI (-0.918938533204672741780329736406)
#define DPI 3.14159265358979323846

// GEMM tiling (warp-MMA, mma.sync m16n8k16 bf16, single split)
#define BM 128
#define BN 256
#define BK 64
#define NCHUNK (DIM / BK)         // 64
#define ROWB 144                  // 64 bf16 = 128B data + 16B pad (conflict-free ldmatrix)
#define B_OFF (128 * ROWB)        // 18432
#define STAGE_BYTES (B_OFF + 256 * ROWB)   // 55296
#define NSTAGE 3
#define SMEM_TOTAL (NSTAGE * STAGE_BYTES)  // 165888

// ---------------- scratch (device globals; no allocations allowed) ----------------
__device__ __nv_bfloat16 g_xb[MROWS * DIM];
__device__ __nv_bfloat16 g_w1t[DIM * DIM];
__device__ __nv_bfloat16 g_w2t[DIM * DIM];
__device__ __nv_bfloat16 g_h1[MROWS * DIM];
__device__ float  g_h2[MROWS * DIM];
__device__ double g_wpart[2][4096];
__device__ double g_spart[4][64];    // b1ss, b2ss, lvp3, lp3 partials
__device__ float  g_scales[4];       // 1/||w1||, 1/||b1||, 1/||w2||, 1/||b2||

// ---------------- PTX helpers ----------------
__device__ __forceinline__ uint32_t smem_u32(const void* p) {
    uint32_t a;
    asm("{ .reg .u64 t; cvta.to.shared.u64 t, %1; cvt.u32.u64 %0, t; }" : "=r"(a) : "l"(p));
    return a;
}
__device__ __forceinline__ void cpasync16(uint32_t dst, const void* src) {
    asm volatile("cp.async.cg.shared.global [%0], [%1], 16;" :: "r"(dst), "l"(src));
}
__device__ __forceinline__ void ldsm4(uint32_t& r0, uint32_t& r1, uint32_t& r2, uint32_t& r3,
                                      uint32_t addr) {
    asm volatile("ldmatrix.sync.aligned.m8n8.x4.shared.b16 {%0,%1,%2,%3}, [%4];"
                 : "=r"(r0), "=r"(r1), "=r"(r2), "=r"(r3) : "r"(addr));
}
__device__ __forceinline__ void mma_bf16(float* c, const uint32_t* a, const uint32_t* b) {
    asm volatile("mma.sync.aligned.m16n8k16.row.col.f32.bf16.bf16.f32 "
                 "{%0,%1,%2,%3}, {%4,%5,%6,%7}, {%8,%9}, {%0,%1,%2,%3};"
                 : "+f"(c[0]), "+f"(c[1]), "+f"(c[2]), "+f"(c[3])
                 : "r"(a[0]), "r"(a[1]), "r"(a[2]), "r"(a[3]), "r"(b[0]), "r"(b[1]));
}

// ---------------- block reduce (deterministic) ----------------
__device__ __forceinline__ double block_reduce_256(double v) {
    __shared__ double sm[256];
    int t = threadIdx.x + threadIdx.y * blockDim.x;
    sm[t] = v;
    __syncthreads();
    for (int s = 128; s > 0; s >>= 1) {
        if (t < s) sm[t] += sm[t + s];
        __syncthreads();
    }
    double r = sm[0];
    __syncthreads();
    return r;
}

// ---------------- fused convert: w1 & w2 (transpose + bf16 + sumsq) and x (bf16) ----------------
__global__ void convert_all_kernel(const float* __restrict__ w1,
                                   const float* __restrict__ w2,
                                   const float4* __restrict__ x) {
    const int tx = threadIdx.x, ty = threadIdx.y;   // (32, 8)
    if (blockIdx.z == 2) {
        // x convert: 4096 blocks x 256 threads = 1M float4s, one each
        const int t = ty * 32 + tx;
        const int i = (blockIdx.y * 64 + blockIdx.x) * 256 + t;
        float4 v = x[i];
        __nv_bfloat162* xb = (__nv_bfloat162*)g_xb;
        xb[i * 2 + 0] = __halves2bfloat162(__float2bfloat16(v.x), __float2bfloat16(v.y));
        xb[i * 2 + 1] = __halves2bfloat162(__float2bfloat16(v.z), __float2bfloat16(v.w));
        return;
    }
    const int slot = blockIdx.z;
    const float* __restrict__ W = slot ? w2 : w1;
    __nv_bfloat16* __restrict__ T = slot ? g_w2t : g_w1t;

    __shared__ float tile[64][65];
    const int k0 = blockIdx.y * 64, n0 = blockIdx.x * 64;
    double ss = 0.0;
#pragma unroll
    for (int rr = 0; rr < 8; rr++) {
        const int kl = ty + rr * 8;
#pragma unroll
        for (int ch = 0; ch < 2; ch++) {
            const int nl = tx + ch * 32;
            float v = W[(size_t)(k0 + kl) * DIM + n0 + nl];
            tile[kl][nl] = v;
            ss += (double)v * (double)v;
        }
    }
    __syncthreads();
#pragma unroll
    for (int rr = 0; rr < 8; rr++) {
        const int nl = ty + rr * 8;
        size_t o = (size_t)(n0 + nl) * DIM + k0 + 2 * tx;
        *(__nv_bfloat162*)(T + o) = __halves2bfloat162(
            __float2bfloat16(tile[2 * tx][nl]),
            __float2bfloat16(tile[2 * tx + 1][nl]));
    }
    double r = block_reduce_256(ss);
    if (tx == 0 && ty == 0) g_wpart[slot][blockIdx.y * 64 + blockIdx.x] = r;
}

// ---------------- parallel small partials ----------------
__global__ void small_partials_kernel(const float* __restrict__ b1, const float* __restrict__ b2,
                                      const float* __restrict__ w3mu, const float* __restrict__ w3rho,
                                      const float* __restrict__ b3mu, const float* __restrict__ b3rho) {
    const int t = threadIdx.x;
    const int g = blockIdx.x * 256 + t;
    const int stride = 64 * 256;
    double a;

    a = 0.0;
    for (int i = g; i < DIM; i += stride) { double x = (double)b1[i]; a += x * x; }
    { double r = block_reduce_256(a); if (t == 0) g_spart[0][blockIdx.x] = r; }

    a = 0.0;
    for (int i = g; i < DIM; i += stride) { double x = (double)b2[i]; a += x * x; }
    { double r = block_reduce_256(a); if (t == 0) g_spart[1][blockIdx.x] = r; }

    a = 0.0;
    for (int i = g; i < NOUT * DIM; i += stride) {
        float r = w3rho[i];
        a += (double)(-0.918938533f - logf(log1pf(expf(r))));
    }
    for (int i = g; i < NOUT; i += stride) {
        float r = b3rho[i];
        a += (double)(-0.918938533f - logf(log1pf(expf(r))));
    }
    { double r = block_reduce_256(a); if (t == 0) g_spart[2][blockIdx.x] = r; }

    a = 0.0;
    for (int i = g; i < NOUT * DIM; i += stride) {
        float m = w3mu[i];
        a += (double)(-0.918938533f - 0.5f * m * m);
    }
    for (int i = g; i < NOUT; i += stride) {
        float m = b3mu[i];
        a += (double)(-0.918938533f - 0.5f * m * m);
    }
    { double r = block_reduce_256(a); if (t == 0) g_spart[3][blockIdx.x] = r; }
}

// ---------------- scalar math ----------------
__device__ double log_C_vmf(double d, double kappa) {
    double s  = 0.5 * d - 1.0;
    double x  = kappa / s;
    double sq = sqrt(1.0 + x * x);
    double eta = sq + log(x) - log1p(sq);
    double lbi = s * eta - 0.5 * log(2.0 * DPI * s) - 0.5 * log(sq);
    return d * NHLOG2PI + s * log(kappa) - lbi;
}
__device__ double log_surf(double d) {
    double h = 0.5 * (d + 1.0);
    return log(2.0) + h * log(DPI) - lgamma(h);
}

// ---------------- finalize: reduce partials + scales + lvp/lp ----------------
__global__ void finalize_kernel(const float* __restrict__ lkw1, const float* __restrict__ lkb1,
                                const float* __restrict__ lkw2, const float* __restrict__ lkb2,
                                float* __restrict__ out_scalars) {
    const int t = threadIdx.x;
    double a;

    a = 0.0; for (int i = t; i < 4096; i += 256) a += g_wpart[0][i];
    double sw1 = block_reduce_256(a);
    a = 0.0; for (int i = t; i < 4096; i += 256) a += g_wpart[1][i];
    double sw2 = block_reduce_256(a);
    a = (t < 64) ? g_spart[0][t] : 0.0;
    double sb1 = block_reduce_256(a);
    a = (t < 64) ? g_spart[1][t] : 0.0;
    double sb2 = block_reduce_256(a);
    a = (t < 64) ? g_spart[2][t] : 0.0;
    double lvp3 = block_reduce_256(a);
    a = (t < 64) ? g_spart[3][t] : 0.0;
    double lp3 = block_reduce_256(a);

    if (t == 0) {
        g_scales[0] = (float)(1.0 / sqrt(sw1));
        g_scales[1] = (float)(1.0 / sqrt(sb1));
        g_scales[2] = (float)(1.0 / sqrt(sw2));
        g_scales[3] = (float)(1.0 / sqrt(sb2));

        double kw1 = exp((double)lkw1[0]) + 1e-6;
        double kb1 = exp((double)lkb1[0]) + 1e-6;
        double kw2 = exp((double)lkw2[0]) + 1e-6;
        double kb2 = exp((double)lkb2[0]) + 1e-6;
        double dw = (double)DIM * (double)DIM;
        double db = (double)DIM;

        double lvp = kw1 + log_C_vmf(dw, kw1) + kb1 + log_C_vmf(db, kb1)
                   + kw2 + log_C_vmf(dw, kw2) + kb2 + log_C_vmf(db, kb2) + lvp3;
        double lp = -4.0 * log_surf(dw) + lp3;   // source bug preserved (all terms use d_w)

        out_scalars[0] = (float)lvp;
        out_scalars[1] = (float)lp;
    }
}

// ---------------- warp-MMA GEMM: C = relu((A @ B^T)*invw + bias*invb) ----------------
// A: [M][K] bf16 (K-major). B: [N][K] bf16 (K-major, pre-transposed weights).
__device__ __forceinline__ void load_stage(uint32_t base,
                                           const __nv_bfloat16* __restrict__ A,
                                           const __nv_bfloat16* __restrict__ B,
                                           int m0, int n0, int k0, int tid) {
#pragma unroll
    for (int q = 0; q < 4; q++) {
        int c = tid + q * 256;                 // 0..1023 : A rows 0..127, 8x16B per row
        int row = c >> 3, c8 = c & 7;
        cpasync16(base + (uint32_t)(row * ROWB + c8 * 16),
                  A + (size_t)(m0 + row) * DIM + k0 + c8 * 8);
    }
#pragma unroll
    for (int q = 0; q < 8; q++) {
        int c = tid + q * 256;                 // 0..2047 : B rows 0..255
        int row = c >> 3, c8 = c & 7;
        cpasync16(base + (uint32_t)(B_OFF + row * ROWB + c8 * 16),
                  B + (size_t)(n0 + row) * DIM + k0 + c8 * 8);
    }
}

__global__ void __launch_bounds__(256)
gemm_kernel(const __nv_bfloat16* __restrict__ A, const __nv_bfloat16* __restrict__ B,
            const float* __restrict__ bias, int sidx, int mode) {
    extern __shared__ char smem[];
    const uint32_t sb = smem_u32(smem);
    const int tid = threadIdx.x, wid = tid >> 5, lane = tid & 31;
    const int wm = wid >> 2, wn = wid & 3;     // 2 x 4 warp grid; warp tile 64x64
    const int m0 = blockIdx.y * BM, n0 = blockIdx.x * BN;

    float acc[4][8][4];
#pragma unroll
    for (int i = 0; i < 4; i++)
#pragma unroll
        for (int j = 0; j < 8; j++)
#pragma unroll
            for (int k = 0; k < 4; k++) acc[i][j][k] = 0.0f;

    // per-thread ldmatrix base addresses (within-stage)
    const uint32_t a_base = sb + (uint32_t)((wm * 64 + (lane & 15)) * ROWB + (lane >> 4) * 16);
    const uint32_t b_base = sb + (uint32_t)(B_OFF +
                         (wn * 64 + ((lane >> 4) & 1) * 8 + (lane & 7)) * ROWB +
                         ((lane >> 3) & 1) * 16);

    // prologue: stages 0, 1
    load_stage(sb, A, B, m0, n0, 0, tid);
    asm volatile("cp.async.commit_group;" ::: "memory");
    load_stage(sb + STAGE_BYTES, A, B, m0, n0, BK, tid);
    asm volatile("cp.async.commit_group;" ::: "memory");

    for (int i = 0; i < NCHUNK; i++) {
        const uint32_t so = (uint32_t)(i % NSTAGE) * STAGE_BYTES;
        if (i == NCHUNK - 1) {
            asm volatile("cp.async.wait_group 0;" ::: "memory");
        } else {
            asm volatile("cp.async.wait_group 1;" ::: "memory");
        }
        __syncthreads();
        if (i + 2 < NCHUNK) {
            load_stage(sb + (uint32_t)((i + 2) % NSTAGE) * STAGE_BYTES,
                       A, B, m0, n0, (i + 2) * BK, tid);
            asm volatile("cp.async.commit_group;" ::: "memory");
        }

        // 4 ks-steps of k16 each; fragments double-buffered across ks
        uint32_t af[2][4][4], bfr[2][4][4];
#pragma unroll
        for (int mt = 0; mt < 4; mt++)
            ldsm4(af[0][mt][0], af[0][mt][1], af[0][mt][2], af[0][mt][3],
                  a_base + so + (uint32_t)(mt * 16 * ROWB));
#pragma unroll
        for (int p = 0; p < 4; p++)
            ldsm4(bfr[0][p][0], bfr[0][p][1], bfr[0][p][2], bfr[0][p][3],
                  b_base + so + (uint32_t)(p * 16 * ROWB));

#pragma unroll
        for (int ks = 0; ks < 4; ks++) {
            const int cur = ks & 1, nxt = cur ^ 1;
            if (ks < 3) {
                const uint32_t kb = (uint32_t)((ks + 1) * 32);
#pragma unroll
                for (int mt = 0; mt < 4; mt++)
                    ldsm4(af[nxt][mt][0], af[nxt][mt][1], af[nxt][mt][2], af[nxt][mt][3],
                          a_base + so + (uint32_t)(mt * 16 * ROWB) + kb);
#pragma unroll
                for (int p = 0; p < 4; p++)
                    ldsm4(bfr[nxt][p][0], bfr[nxt][p][1], bfr[nxt][p][2], bfr[nxt][p][3],
                          b_base + so + (uint32_t)(p * 16 * ROWB) + kb);
            }
#pragma unroll
            for (int mt = 0; mt < 4; mt++)
#pragma unroll
                for (int nt = 0; nt < 8; nt++)
                    mma_bf16(acc[mt][nt], af[cur][mt], &bfr[cur][nt >> 1][(nt & 1) * 2]);
        }
    }

    // ------- epilogue: scale + bias + relu; direct fragment stores -------
    const float invw = g_scales[sidx];
    const float invb = g_scales[sidx + 1];
#pragma unroll
    for (int mt = 0; mt < 4; mt++) {
        const int r0 = m0 + wm * 64 + mt * 16 + (lane >> 2);
#pragma unroll
        for (int nt = 0; nt < 8; nt++) {
            const int col = n0 + wn * 64 + nt * 8 + 2 * (lane & 3);
            const float bv0 = bias[col] * invb;
            const float bv1 = bias[col + 1] * invb;
            float v00 = fmaxf(acc[mt][nt][0] * invw + bv0, 0.0f);
            float v01 = fmaxf(acc[mt][nt][1] * invw + bv1, 0.0f);
            float v10 = fmaxf(acc[mt][nt][2] * invw + bv0, 0.0f);
            float v11 = fmaxf(acc[mt][nt][3] * invw + bv1, 0.0f);
            const size_t o0 = (size_t)r0 * DIM + col;
            const size_t o1 = (size_t)(r0 + 8) * DIM + col;
            if (mode == 0) {
                *(__nv_bfloat162*)(g_h1 + o0) =
                    __halves2bfloat162(__float2bfloat16(v00), __float2bfloat16(v01));
                *(__nv_bfloat162*)(g_h1 + o1) =
                    __halves2bfloat162(__float2bfloat16(v10), __float2bfloat16(v11));
            } else {
                *(float2*)(g_h2 + o0) = make_float2(v00, v01);
                *(float2*)(g_h2 + o1) = make_float2(v10, v11);
            }
        }
    }
}

// ---------------- layer 3 (tiny GEMM) + log_softmax, one warp per row ----------------
__global__ void layer3_kernel(const float* __restrict__ w3,
                              const float* __restrict__ b3,
                              float* __restrict__ out) {
    const int warp = threadIdx.x >> 5;
    const int lane = threadIdx.x & 31;
    const int row = blockIdx.x * (blockDim.x >> 5) + warp;
    if (row >= MROWS) return;

    float acc[NOUT] = {0.f, 0.f, 0.f, 0.f, 0.f};
    const float* hrow = g_h2 + (size_t)row * DIM;
    for (int k = lane; k < DIM; k += 32) {
        float h = hrow[k];
#pragma unroll
        for (int o = 0; o < NOUT; o++) acc[o] += h * w3[o * DIM + k];
    }
#pragma unroll
    for (int o = 0; o < NOUT; o++)
#pragma unroll
        for (int off = 16; off > 0; off >>= 1)
            acc[o] += __shfl_xor_sync(0xffffffffu, acc[o], off);

    if (lane == 0) {
        float y[NOUT];
        float m = -1e30f;
#pragma unroll
        for (int o = 0; o < NOUT; o++) {
            y[o] = acc[o] + b3[o];
            m = fmaxf(m, y[o]);
        }
        float s = 0.0f;
#pragma unroll
        for (int o = 0; o < NOUT; o++) s += expf(y[o] - m);
        float lse = m + logf(s);
#pragma unroll
        for (int o = 0; o < NOUT; o++) out[row * NOUT + o] = y[o] - lse;
    }
}

// ---------------- launch ----------------
extern "C" void kernel_launch(void* const* d_in, const int* in_sizes, int n_in,
                              void* d_out, int out_size) {
    const float* x     = (const float*)d_in[0];
    const float* w1    = (const float*)d_in[1];
    const float* lkw1  = (const float*)d_in[2];
    const float* b1    = (const float*)d_in[3];
    const float* lkb1  = (const float*)d_in[4];
    const float* w2    = (const float*)d_in[5];
    const float* lkw2  = (const float*)d_in[6];
    const float* b2    = (const float*)d_in[7];
    const float* lkb2  = (const float*)d_in[8];
    const float* w3mu  = (const float*)d_in[9];
    const float* w3rho = (const float*)d_in[10];
    const float* b3mu  = (const float*)d_in[11];
    const float* b3rho = (const float*)d_in[12];
    float* out = (float*)d_out;

    static bool attr_done = false;
    if (!attr_done) {
        cudaFuncSetAttribute(gemm_kernel, cudaFuncAttributeMaxDynamicSharedMemorySize, SMEM_TOTAL);
        attr_done = true;
    }

    __nv_bfloat16 *p_xb, *p_w1t, *p_w2t, *p_h1;
    cudaGetSymbolAddress((void**)&p_xb,  g_xb);
    cudaGetSymbolAddress((void**)&p_w1t, g_w1t);
    cudaGetSymbolAddress((void**)&p_w2t, g_w2t);
    cudaGetSymbolAddress((void**)&p_h1,  g_h1);

    // launch 0: fused conversions (w1, w2 transposed bf16 + sumsq partials; x bf16)
    convert_all_kernel<<<dim3(64, 64, 3), dim3(32, 8)>>>(w1, w2, (const float4*)x);
    // launch 1-2: scalar path
    small_partials_kernel<<<64, 256>>>(b1, b2, w3mu, w3rho, b3mu, b3rho);
    finalize_kernel<<<1, 256>>>(lkw1, lkb1, lkw2, lkb2, out + (out_size - 2));
    // launch 3-4: GEMMs (launch index 3 = gemm1 → gets ncu profile)
    dim3 grid(DIM / BN, MROWS / BM);   // (16, 8) = 128 CTAs
    gemm_kernel<<<grid, 256, SMEM_TOTAL>>>(p_xb, p_w1t, b1, 0, 0);
    gemm_kernel<<<grid, 256, SMEM_TOTAL>>>(p_h1, p_w2t, b2, 2, 1);
    // launch 5: tiny layer 3 + log_softmax
    layer3_kernel<<<128, 256>>>(w3mu, b3mu, out);
}

// round 8
// speedup vs baseline: 7.2703x; 1.4390x over previous
#include <cuda_runtime.h>
#include <cuda_bf16.h>
#include <math.h>
#include <stdint.h>

#define MROWS 1024
#define DIM   4096
#define NOUT  5
#define NHLOG2PI (-0.918938533204672741780329736406)
#define DPI 3.14159265358979323846

// GEMM tiling (warp-MMA, mma.sync m16n8k16 bf16, single split)
#define BM 128
#define BN 256
#define BK 64
#define NCHUNK (DIM / BK)         // 64
#define ROWB 144                  // 64 bf16 = 128B data + 16B pad (conflict-free ldmatrix)
#define B_OFF (128 * ROWB)        // 18432
#define STAGE_BYTES (B_OFF + 256 * ROWB)   // 55296
#define NSTAGE 3
#define SMEM_TOTAL (NSTAGE * STAGE_BYTES)  // 165888

// ---------------- scratch (device globals; no allocations allowed) ----------------
__device__ __nv_bfloat16 g_xb[MROWS * DIM];
__device__ __nv_bfloat16 g_w1t[DIM * DIM];
__device__ __nv_bfloat16 g_w2t[DIM * DIM];
__device__ __nv_bfloat16 g_h1[MROWS * DIM];
__device__ float  g_h2[MROWS * DIM];
__device__ double g_wpart[2][4096];
__device__ double g_spart[4][64];    // b1ss, b2ss, lvp3, lp3 partials
__device__ float  g_scales[4];       // 1/||w1||, 1/||b1||, 1/||w2||, 1/||b2||

// ---------------- PTX helpers ----------------
__device__ __forceinline__ uint32_t smem_u32(const void* p) {
    uint32_t a;
    asm("{ .reg .u64 t; cvta.to.shared.u64 t, %1; cvt.u32.u64 %0, t; }" : "=r"(a) : "l"(p));
    return a;
}
__device__ __forceinline__ void cpasync16(uint32_t dst, const void* src) {
    asm volatile("cp.async.cg.shared.global [%0], [%1], 16;" :: "r"(dst), "l"(src));
}
__device__ __forceinline__ void ldsm4(uint32_t& r0, uint32_t& r1, uint32_t& r2, uint32_t& r3,
                                      uint32_t addr) {
    asm volatile("ldmatrix.sync.aligned.m8n8.x4.shared.b16 {%0,%1,%2,%3}, [%4];"
                 : "=r"(r0), "=r"(r1), "=r"(r2), "=r"(r3) : "r"(addr));
}
__device__ __forceinline__ void mma_bf16(float* c, const uint32_t* a, const uint32_t* b) {
    asm volatile("mma.sync.aligned.m16n8k16.row.col.f32.bf16.bf16.f32 "
                 "{%0,%1,%2,%3}, {%4,%5,%6,%7}, {%8,%9}, {%0,%1,%2,%3};"
                 : "+f"(c[0]), "+f"(c[1]), "+f"(c[2]), "+f"(c[3])
                 : "r"(a[0]), "r"(a[1]), "r"(a[2]), "r"(a[3]), "r"(b[0]), "r"(b[1]));
}

// ---------------- block reduce (deterministic) ----------------
__device__ __forceinline__ double block_reduce_256(double v) {
    __shared__ double sm[256];
    int t = threadIdx.x + threadIdx.y * blockDim.x;
    sm[t] = v;
    __syncthreads();
    for (int s = 128; s > 0; s >>= 1) {
        if (t < s) sm[t] += sm[t + s];
        __syncthreads();
    }
    double r = sm[0];
    __syncthreads();
    return r;
}

// ---------------- fused convert: w1 & w2 (transpose + bf16 + fp32 sumsq) and x (bf16) ----------------
__global__ void convert_all_kernel(const float* __restrict__ w1,
                                   const float* __restrict__ w2,
                                   const float4* __restrict__ x) {
    const int tx = threadIdx.x, ty = threadIdx.y;   // (32, 8)
    if (blockIdx.z == 2) {
        const int t = ty * 32 + tx;
        const int i = (blockIdx.y * 64 + blockIdx.x) * 256 + t;
        float4 v = x[i];
        __nv_bfloat162* xb = (__nv_bfloat162*)g_xb;
        xb[i * 2 + 0] = __halves2bfloat162(__float2bfloat16(v.x), __float2bfloat16(v.y));
        xb[i * 2 + 1] = __halves2bfloat162(__float2bfloat16(v.z), __float2bfloat16(v.w));
        return;
    }
    const int slot = blockIdx.z;
    const float* __restrict__ W = slot ? w2 : w1;
    __nv_bfloat16* __restrict__ T = slot ? g_w2t : g_w1t;

    __shared__ float tile[64][65];
    const int k0 = blockIdx.y * 64, n0 = blockIdx.x * 64;
    float ss = 0.0f;    // fp32 partial over 16 elems (rel err ~2e-7, negligible)
#pragma unroll
    for (int rr = 0; rr < 8; rr++) {
        const int kl = ty + rr * 8;
#pragma unroll
        for (int ch = 0; ch < 2; ch++) {
            const int nl = tx + ch * 32;
            float v = W[(size_t)(k0 + kl) * DIM + n0 + nl];
            tile[kl][nl] = v;
            ss = fmaf(v, v, ss);
        }
    }
    __syncthreads();
#pragma unroll
    for (int rr = 0; rr < 8; rr++) {
        const int nl = ty + rr * 8;
        size_t o = (size_t)(n0 + nl) * DIM + k0 + 2 * tx;
        *(__nv_bfloat162*)(T + o) = __halves2bfloat162(
            __float2bfloat16(tile[2 * tx][nl]),
            __float2bfloat16(tile[2 * tx + 1][nl]));
    }
    double r = block_reduce_256((double)ss);
    if (tx == 0 && ty == 0) g_wpart[slot][blockIdx.y * 64 + blockIdx.x] = r;
}

// ---------------- parallel small partials ----------------
__global__ void small_partials_kernel(const float* __restrict__ b1, const float* __restrict__ b2,
                                      const float* __restrict__ w3mu, const float* __restrict__ w3rho,
                                      const float* __restrict__ b3mu, const float* __restrict__ b3rho) {
    const int t = threadIdx.x;
    const int g = blockIdx.x * 256 + t;
    const int stride = 64 * 256;
    double a;

    a = 0.0;
    for (int i = g; i < DIM; i += stride) { double x = (double)b1[i]; a += x * x; }
    { double r = block_reduce_256(a); if (t == 0) g_spart[0][blockIdx.x] = r; }

    a = 0.0;
    for (int i = g; i < DIM; i += stride) { double x = (double)b2[i]; a += x * x; }
    { double r = block_reduce_256(a); if (t == 0) g_spart[1][blockIdx.x] = r; }

    a = 0.0;
    for (int i = g; i < NOUT * DIM; i += stride) {
        float r = w3rho[i];
        a += (double)(-0.918938533f - logf(log1pf(expf(r))));
    }
    for (int i = g; i < NOUT; i += stride) {
        float r = b3rho[i];
        a += (double)(-0.918938533f - logf(log1pf(expf(r))));
    }
    { double r = block_reduce_256(a); if (t == 0) g_spart[2][blockIdx.x] = r; }

    a = 0.0;
    for (int i = g; i < NOUT * DIM; i += stride) {
        float m = w3mu[i];
        a += (double)(-0.918938533f - 0.5f * m * m);
    }
    for (int i = g; i < NOUT; i += stride) {
        float m = b3mu[i];
        a += (double)(-0.918938533f - 0.5f * m * m);
    }
    { double r = block_reduce_256(a); if (t == 0) g_spart[3][blockIdx.x] = r; }
}

// ---------------- scalar math ----------------
__device__ double log_C_vmf(double d, double kappa) {
    double s  = 0.5 * d - 1.0;
    double x  = kappa / s;
    double sq = sqrt(1.0 + x * x);
    double eta = sq + log(x) - log1p(sq);
    double lbi = s * eta - 0.5 * log(2.0 * DPI * s) - 0.5 * log(sq);
    return d * NHLOG2PI + s * log(kappa) - lbi;
}
__device__ double log_surf(double d) {
    double h = 0.5 * (d + 1.0);
    return log(2.0) + h * log(DPI) - lgamma(h);
}

// ---------------- finalize: reduce partials + scales + lvp/lp ----------------
__global__ void finalize_kernel(const float* __restrict__ lkw1, const float* __restrict__ lkb1,
                                const float* __restrict__ lkw2, const float* __restrict__ lkb2,
                                float* __restrict__ out_scalars) {
    const int t = threadIdx.x;
    double a;

    a = 0.0; for (int i = t; i < 4096; i += 256) a += g_wpart[0][i];
    double sw1 = block_reduce_256(a);
    a = 0.0; for (int i = t; i < 4096; i += 256) a += g_wpart[1][i];
    double sw2 = block_reduce_256(a);
    a = (t < 64) ? g_spart[0][t] : 0.0;
    double sb1 = block_reduce_256(a);
    a = (t < 64) ? g_spart[1][t] : 0.0;
    double sb2 = block_reduce_256(a);
    a = (t < 64) ? g_spart[2][t] : 0.0;
    double lvp3 = block_reduce_256(a);
    a = (t < 64) ? g_spart[3][t] : 0.0;
    double lp3 = block_reduce_256(a);

    if (t == 0) {
        g_scales[0] = (float)(1.0 / sqrt(sw1));
        g_scales[1] = (float)(1.0 / sqrt(sb1));
        g_scales[2] = (float)(1.0 / sqrt(sw2));
        g_scales[3] = (float)(1.0 / sqrt(sb2));

        double kw1 = exp((double)lkw1[0]) + 1e-6;
        double kb1 = exp((double)lkb1[0]) + 1e-6;
        double kw2 = exp((double)lkw2[0]) + 1e-6;
        double kb2 = exp((double)lkb2[0]) + 1e-6;
        double dw = (double)DIM * (double)DIM;
        double db = (double)DIM;

        double lvp = kw1 + log_C_vmf(dw, kw1) + kb1 + log_C_vmf(db, kb1)
                   + kw2 + log_C_vmf(dw, kw2) + kb2 + log_C_vmf(db, kb2) + lvp3;
        double lp = -4.0 * log_surf(dw) + lp3;   // source bug preserved (all terms use d_w)

        out_scalars[0] = (float)lvp;
        out_scalars[1] = (float)lp;
    }
}

// ---------------- warp-MMA GEMM: C = relu((A @ B^T)*invw + bias*invb) ----------------
// A: [M][K] bf16 (K-major). B: [N][K] bf16 (K-major, pre-transposed weights).
__device__ __forceinline__ void load_stage(uint32_t base,
                                           const __nv_bfloat16* __restrict__ A,
                                           const __nv_bfloat16* __restrict__ B,
                                           int m0, int n0, int k0, int tid) {
#pragma unroll
    for (int q = 0; q < 4; q++) {
        int c = tid + q * 256;                 // A rows 0..127, 8x16B per row
        int row = c >> 3, c8 = c & 7;
        cpasync16(base + (uint32_t)(row * ROWB + c8 * 16),
                  A + (size_t)(m0 + row) * DIM + k0 + c8 * 8);
    }
#pragma unroll
    for (int q = 0; q < 8; q++) {
        int c = tid + q * 256;                 // B rows 0..255
        int row = c >> 3, c8 = c & 7;
        cpasync16(base + (uint32_t)(B_OFF + row * ROWB + c8 * 16),
                  B + (size_t)(n0 + row) * DIM + k0 + c8 * 8);
    }
}

__device__ __forceinline__ void frag_load(uint32_t (&af)[4][4], uint32_t (&bfr)[4][4],
                                          uint32_t a_base, uint32_t b_base,
                                          uint32_t so, uint32_t kb) {
#pragma unroll
    for (int mt = 0; mt < 4; mt++)
        ldsm4(af[mt][0], af[mt][1], af[mt][2], af[mt][3],
              a_base + so + (uint32_t)(mt * 16 * ROWB) + kb);
#pragma unroll
    for (int p = 0; p < 4; p++)
        ldsm4(bfr[p][0], bfr[p][1], bfr[p][2], bfr[p][3],
              b_base + so + (uint32_t)(p * 16 * ROWB) + kb);
}

__global__ void __launch_bounds__(256)
gemm_kernel(const __nv_bfloat16* __restrict__ A, const __nv_bfloat16* __restrict__ B,
            const float* __restrict__ bias, int sidx, int mode) {
    extern __shared__ char smem[];
    const uint32_t sb = smem_u32(smem);
    const int tid = threadIdx.x, wid = tid >> 5, lane = tid & 31;
    const int wm = wid >> 2, wn = wid & 3;     // 2 x 4 warp grid; warp tile 64x64
    const int m0 = blockIdx.y * BM, n0 = blockIdx.x * BN;

    float acc[4][8][4];
#pragma unroll
    for (int i = 0; i < 4; i++)
#pragma unroll
        for (int j = 0; j < 8; j++)
#pragma unroll
            for (int k = 0; k < 4; k++) acc[i][j][k] = 0.0f;

    const uint32_t a_base = sb + (uint32_t)((wm * 64 + (lane & 15)) * ROWB + (lane >> 4) * 16);
    const uint32_t b_base = sb + (uint32_t)(B_OFF +
                         (wn * 64 + ((lane >> 4) & 1) * 8 + (lane & 7)) * ROWB +
                         ((lane >> 3) & 1) * 16);

    // prologue: stages 0, 1 in flight; wait for stage 0; preload first fragments
    load_stage(sb, A, B, m0, n0, 0, tid);
    asm volatile("cp.async.commit_group;" ::: "memory");
    load_stage(sb + STAGE_BYTES, A, B, m0, n0, BK, tid);
    asm volatile("cp.async.commit_group;" ::: "memory");
    asm volatile("cp.async.wait_group 1;" ::: "memory");
    __syncthreads();

    uint32_t af[2][4][4], bfr[2][4][4];
    frag_load(af[0], bfr[0], a_base, b_base, 0, 0);

    for (int i = 0; i < NCHUNK; i++) {
        const uint32_t so = (uint32_t)(i % NSTAGE) * STAGE_BYTES;
        const uint32_t so_next = (uint32_t)((i + 1) % NSTAGE) * STAGE_BYTES;
        // stage (i+2)%3 == (i-1)%3: all its ldsm reads finished before chunk i-1's
        // ks==3 barrier, which precedes this point — safe to overwrite.
        if (i + 2 < NCHUNK) {
            load_stage(sb + (uint32_t)((i + 2) % NSTAGE) * STAGE_BYTES,
                       A, B, m0, n0, (i + 2) * BK, tid);
            asm volatile("cp.async.commit_group;" ::: "memory");
        }

#pragma unroll
        for (int ks = 0; ks < 4; ks++) {
            const int cur = ks & 1, nxt = cur ^ 1;
            if (ks < 3) {
                frag_load(af[nxt], bfr[nxt], a_base, b_base, so, (uint32_t)((ks + 1) * 32));
            } else if (i + 1 < NCHUNK) {
                // make stage i+1 visible to all threads, then prefetch its ks=0
                // fragments BEFORE issuing this chunk's last MMA group
                if (i + 2 < NCHUNK) {
                    asm volatile("cp.async.wait_group 1;" ::: "memory");
                } else {
                    asm volatile("cp.async.wait_group 0;" ::: "memory");
                }
                __syncthreads();
                frag_load(af[nxt], bfr[nxt], a_base, b_base, so_next, 0);
            }
#pragma unroll
            for (int mt = 0; mt < 4; mt++)
#pragma unroll
                for (int nt = 0; nt < 8; nt++)
                    mma_bf16(acc[mt][nt], af[cur][mt], &bfr[cur][nt >> 1][(nt & 1) * 2]);
        }
    }

    // ------- epilogue: scale + bias + relu; direct fragment stores -------
    const float invw = g_scales[sidx];
    const float invb = g_scales[sidx + 1];
#pragma unroll
    for (int mt = 0; mt < 4; mt++) {
        const int r0 = m0 + wm * 64 + mt * 16 + (lane >> 2);
#pragma unroll
        for (int nt = 0; nt < 8; nt++) {
            const int col = n0 + wn * 64 + nt * 8 + 2 * (lane & 3);
            const float bv0 = bias[col] * invb;
            const float bv1 = bias[col + 1] * invb;
            float v00 = fmaxf(acc[mt][nt][0] * invw + bv0, 0.0f);
            float v01 = fmaxf(acc[mt][nt][1] * invw + bv1, 0.0f);
            float v10 = fmaxf(acc[mt][nt][2] * invw + bv0, 0.0f);
            float v11 = fmaxf(acc[mt][nt][3] * invw + bv1, 0.0f);
            const size_t o0 = (size_t)r0 * DIM + col;
            const size_t o1 = (size_t)(r0 + 8) * DIM + col;
            if (mode == 0) {
                *(__nv_bfloat162*)(g_h1 + o0) =
                    __halves2bfloat162(__float2bfloat16(v00), __float2bfloat16(v01));
                *(__nv_bfloat162*)(g_h1 + o1) =
                    __halves2bfloat162(__float2bfloat16(v10), __float2bfloat16(v11));
            } else {
                *(float2*)(g_h2 + o0) = make_float2(v00, v01);
                *(float2*)(g_h2 + o1) = make_float2(v10, v11);
            }
        }
    }
}

// ---------------- layer 3 (tiny GEMM) + log_softmax, one warp per row ----------------
__global__ void layer3_kernel(const float* __restrict__ w3,
                              const float* __restrict__ b3,
                              float* __restrict__ out) {
    const int warp = threadIdx.x >> 5;
    const int lane = threadIdx.x & 31;
    const int row = blockIdx.x * (blockDim.x >> 5) + warp;
    if (row >= MROWS) return;

    float acc[NOUT] = {0.f, 0.f, 0.f, 0.f, 0.f};
    const float* hrow = g_h2 + (size_t)row * DIM;
    for (int k = lane; k < DIM; k += 32) {
        float h = hrow[k];
#pragma unroll
        for (int o = 0; o < NOUT; o++) acc[o] += h * w3[o * DIM + k];
    }
#pragma unroll
    for (int o = 0; o < NOUT; o++)
#pragma unroll
        for (int off = 16; off > 0; off >>= 1)
            acc[o] += __shfl_xor_sync(0xffffffffu, acc[o], off);

    if (lane == 0) {
        float y[NOUT];
        float m = -1e30f;
#pragma unroll
        for (int o = 0; o < NOUT; o++) {
            y[o] = acc[o] + b3[o];
            m = fmaxf(m, y[o]);
        }
        float s = 0.0f;
#pragma unroll
        for (int o = 0; o < NOUT; o++) s += expf(y[o] - m);
        float lse = m + logf(s);
#pragma unroll
        for (int o = 0; o < NOUT; o++) out[row * NOUT + o] = y[o] - lse;
    }
}

// ---------------- launch ----------------
extern "C" void kernel_launch(void* const* d_in, const int* in_sizes, int n_in,
                              void* d_out, int out_size) {
    const float* x     = (const float*)d_in[0];
    const float* w1    = (const float*)d_in[1];
    const float* lkw1  = (const float*)d_in[2];
    const float* b1    = (const float*)d_in[3];
    const float* lkb1  = (const float*)d_in[4];
    const float* w2    = (const float*)d_in[5];
    const float* lkw2  = (const float*)d_in[6];
    const float* b2    = (const float*)d_in[7];
    const float* lkb2  = (const float*)d_in[8];
    const float* w3mu  = (const float*)d_in[9];
    const float* w3rho = (const float*)d_in[10];
    const float* b3mu  = (const float*)d_in[11];
    const float* b3rho = (const float*)d_in[12];
    float* out = (float*)d_out;

    static bool attr_done = false;
    if (!attr_done) {
        cudaFuncSetAttribute(gemm_kernel, cudaFuncAttributeMaxDynamicSharedMemorySize, SMEM_TOTAL);
        attr_done = true;
    }

    __nv_bfloat16 *p_xb, *p_w1t, *p_w2t, *p_h1;
    cudaGetSymbolAddress((void**)&p_xb,  g_xb);
    cudaGetSymbolAddress((void**)&p_w1t, g_w1t);
    cudaGetSymbolAddress((void**)&p_w2t, g_w2t);
    cudaGetSymbolAddress((void**)&p_h1,  g_h1);

    // launch 0: fused conversions (w1, w2 transposed bf16 + fp32 sumsq partials; x bf16)
    convert_all_kernel<<<dim3(64, 64, 3), dim3(32, 8)>>>(w1, w2, (const float4*)x);
    // launch 1-2: scalar path
    small_partials_kernel<<<64, 256>>>(b1, b2, w3mu, w3rho, b3mu, b3rho);
    finalize_kernel<<<1, 256>>>(lkw1, lkb1, lkw2, lkb2, out + (out_size - 2));
    // launch 3-4: GEMMs (launch index 3 = gemm1 → gets ncu profile)
    dim3 grid(DIM / BN, MROWS / BM);   // (16, 8) = 128 CTAs
    gemm_kernel<<<grid, 256, SMEM_TOTAL>>>(p_xb, p_w1t, b1, 0, 0);
    gemm_kernel<<<grid, 256, SMEM_TOTAL>>>(p_h1, p_w2t, b2, 2, 1);
    // launch 5: tiny layer 3 + log_softmax
    layer3_kernel<<<128, 256>>>(w3mu, b3mu, out);
}